// round 11
// baseline (speedup 1.0000x reference)
#include <cuda_runtime.h>

#define BB 16
#define DDIM 4096
#define HH 32
#define HKV 8
#define DH 128
#define REP 4
#define LL 4096
#define QK_COLS (HH*DH + HKV*DH)   // 5120
#define NSPLIT 16
#define SPLIT_LEN (LL/NSPLIT)      // 256
#define NDCH 64
#define DCH (DDIM/NDCH)            // 64

typedef unsigned long long ULL;

// ---------------- scratch ----------------
__device__ float g_qk_raw[BB][QK_COLS];   // REDG-accumulated raw projections (left zeroed by rope)
__device__ float g_q[BB][HH][DH];         // roped q, pre-scaled by log2(e)/sqrt(128)
__device__ float g_knew[BB][HKV][DH];
__device__ float g_ao[BB][HH*DH];
__device__ float g_l[BB*HH];

// ---------------- helpers ----------------
__device__ __forceinline__ ULL pack2(float lo, float hi) {
    ULL r;
    asm("mov.b64 %0, {%1, %2};" : "=l"(r) : "f"(lo), "f"(hi));
    return r;
}
__device__ __forceinline__ void unpack2(ULL v, float& lo, float& hi) {
    asm("mov.b64 {%0, %1}, %2;" : "=f"(lo), "=f"(hi) : "l"(v));
}
__device__ __forceinline__ ULL ffma2(ULL a, ULL b, ULL c) {
    ULL d;
    asm("fma.rn.f32x2 %0, %1, %2, %3;" : "=l"(d) : "l"(a), "l"(b), "l"(c));
    return d;
}
__device__ __forceinline__ float ex2(float x) {
    float r;
    asm("ex2.approx.f32 %0, %1;" : "=f"(r) : "f"(x));
    return r;
}

// ---------------- kernel 1: fused Q/K projection (colpair, z=2, REDG out) ----------------
// grid (10, 64, 2), block 128.
__global__ void __launch_bounds__(128) proj_qk_kernel(const float* __restrict__ x,
                                                      const float* __restrict__ wq,
                                                      const float* __restrict__ wk) {
    __shared__ ULL xs2[DCH][10];
    const int d0 = blockIdx.y * DCH;
    const int b0 = blockIdx.z * 8;

    {
        int i  = threadIdx.x;          // 128 items: 8 batches x 16 float4
        int b  = i / (DCH / 4);
        int d4 = i % (DCH / 4);
        float4 v = *(const float4*)(x + (size_t)(b0 + b) * DDIM + d0 + d4 * 4);
        xs2[d4 * 4 + 0][b] = pack2(v.x, v.x);
        xs2[d4 * 4 + 1][b] = pack2(v.y, v.y);
        xs2[d4 * 4 + 2][b] = pack2(v.z, v.z);
        xs2[d4 * 4 + 3][b] = pack2(v.w, v.w);
    }
    __syncthreads();

    const int col = (blockIdx.x * 128 + threadIdx.x) * 4;
    const float* w;
    int stride;
    if (col < HH * DH) { w = wq + col;              stride = HH * DH; }
    else               { w = wk + (col - HH * DH);  stride = HKV * DH; }
    w += (size_t)d0 * stride;

    ULL acc[8][2];
#pragma unroll
    for (int b = 0; b < 8; b++) { acc[b][0] = 0ULL; acc[b][1] = 0ULL; }

    for (int dd = 0; dd < DCH; dd += 4) {
        float4 wv[4];
#pragma unroll
        for (int u = 0; u < 4; u++)
            wv[u] = *(const float4*)(w + (size_t)(dd + u) * stride);
#pragma unroll
        for (int u = 0; u < 4; u++) {
            ULL wA = ((const ULL*)&wv[u])[0];
            ULL wB = ((const ULL*)&wv[u])[1];
#pragma unroll
            for (int bp = 0; bp < 4; bp++) {
                ulonglong2 xv = *(const ulonglong2*)&xs2[dd + u][2 * bp];
                acc[2*bp    ][0] = ffma2(xv.x, wA, acc[2*bp    ][0]);
                acc[2*bp    ][1] = ffma2(xv.x, wB, acc[2*bp    ][1]);
                acc[2*bp + 1][0] = ffma2(xv.y, wA, acc[2*bp + 1][0]);
                acc[2*bp + 1][1] = ffma2(xv.y, wB, acc[2*bp + 1][1]);
            }
        }
    }

#pragma unroll
    for (int b = 0; b < 8; b++) {
        float c0, c1, c2, c3;
        unpack2(acc[b][0], c0, c1);
        unpack2(acc[b][1], c2, c3);
        atomicAdd(&g_qk_raw[b0 + b][col + 0], c0);
        atomicAdd(&g_qk_raw[b0 + b][col + 1], c1);
        atomicAdd(&g_qk_raw[b0 + b][col + 2], c2);
        atomicAdd(&g_qk_raw[b0 + b][col + 3], c3);
    }
}

// ---------------- kernel 2: RoPE from g_qk_raw (re-zeroes it); zero g_ao/g_l/out ----------------
__global__ void rope_kernel(const float* __restrict__ fc, const float* __restrict__ fs,
                            float* __restrict__ out) {
    int idx = blockIdx.x * blockDim.x + threadIdx.x;
    const int TOT = BB * QK_COLS / 2;                  // 40960
    if (idx >= TOT) return;

    if (idx < BB * HH * DH / 2) {
        *(float2*)&(((float*)g_ao)[idx * 2]) = make_float2(0.f, 0.f);
        *(float2*)&out[idx * 2]              = make_float2(0.f, 0.f);   // BB*DDIM/2 == 32768
    }
    if (idx < BB * HH) g_l[idx] = 0.f;

    int b   = idx / (QK_COLS / 2);
    int col = (idx % (QK_COLS / 2)) * 2;

    float2 v = *(const float2*)&g_qk_raw[b][col];
    *(float2*)&g_qk_raw[b][col] = make_float2(0.f, 0.f);    // reset for next replay
    float e = v.x, o = v.y;

    int p = (col & (DH - 1)) >> 1;
    float c = fc[p], s = fs[p];
    float re = e * c - o * s;
    float ro = e * s + o * c;

    if (col < HH * DH) {
        const float sc = 0.1275174260809843f;   // log2(e)/sqrt(128): scores in log2 domain
        ((float*)g_q)[b * HH * DH + col]     = re * sc;
        ((float*)g_q)[b * HH * DH + col + 1] = ro * sc;
    } else {
        int kc = col - HH * DH;
        ((float*)g_knew)[b * HKV * DH + kc]     = re;
        ((float*)g_knew)[b * HKV * DH + kc + 1] = ro;
    }
}

// ---------------- kernel 3: flash-decode attention (V == K), no-max softmax ----------------
// grid (B*HKV, NSPLIT), block 128 (4 warps), occupancy 5 (20 warps/SM).
// rg = lane>>4, dl = lane&15 (dims dl*4.., 64+dl*4..). q/acc in NATURAL dim pairs
// (k ULLs are free reinterprets — zero k packs); R8 butterfly; exp via raw ex2.
__global__ void __launch_bounds__(128, 5) attn_kernel(const float* __restrict__ cache_k) {
    const int b     = blockIdx.x / HKV;
    const int kv    = blockIdx.x % HKV;
    const int split = blockIdx.y;
    const int warp  = threadIdx.x >> 5;
    const int lane  = threadIdx.x & 31;
    const int rg    = lane >> 4;
    const int dl    = lane & 15;

    // q natural dim-pairs: qd[h][0..1] = dims dl*4 pairs, [2..3] = dims 64+dl*4 pairs
    ULL qd[4][4];
#pragma unroll
    for (int h = 0; h < 4; h++) {
        float4 a0 = *(const float4*)&g_q[b][kv*REP + h][dl * 4];
        float4 a1 = *(const float4*)&g_q[b][kv*REP + h][64 + dl * 4];
        qd[h][0] = ((const ULL*)&a0)[0];
        qd[h][1] = ((const ULL*)&a0)[1];
        qd[h][2] = ((const ULL*)&a1)[0];
        qd[h][3] = ((const ULL*)&a1)[1];
    }

    // acc natural dim-pairs per head
    ULL acc[4][4];
#pragma unroll
    for (int h = 0; h < 4; h++)
#pragma unroll
        for (int j = 0; j < 4; j++) acc[h][j] = 0ULL;
    float l[4] = {0.f, 0.f, 0.f, 0.f};

    const float* kbase = cache_k + (size_t)b * LL * (HKV * DH) + kv * DH;
    const float* knewp = &g_knew[b][kv][0];
    const int s0 = split * SPLIT_LEN + warp * (SPLIT_LEN / 4) + rg;   // 64 rows per warp

#pragma unroll 2
    for (int i = 0; i < SPLIT_LEN / 8; i++) {       // 32 iters, 2 rows each
        int s = s0 + i * 2;
        const float* rp = (s == LL - 1) ? knewp : (kbase + (size_t)s * (HKV * DH));
        float4 k0 = *(const float4*)(rp + dl * 4);
        float4 k1 = *(const float4*)(rp + 64 + dl * 4);
        ULL kp[4];
        kp[0] = ((const ULL*)&k0)[0];
        kp[1] = ((const ULL*)&k0)[1];
        kp[2] = ((const ULL*)&k1)[0];
        kp[3] = ((const ULL*)&k1)[1];

        // partial scores (pair-folded), log2 domain
        float s0f, s1f, s2f, s3f;
        {
            ULL sp0 = 0ULL, sp1 = 0ULL, sp2 = 0ULL, sp3 = 0ULL;
#pragma unroll
            for (int j = 0; j < 4; j++) {
                sp0 = ffma2(qd[0][j], kp[j], sp0);
                sp1 = ffma2(qd[1][j], kp[j], sp1);
                sp2 = ffma2(qd[2][j], kp[j], sp2);
                sp3 = ffma2(qd[3][j], kp[j], sp3);
            }
            float x, y;
            unpack2(sp0, x, y); s0f = x + y;
            unpack2(sp1, x, y); s1f = x + y;
            unpack2(sp2, x, y); s2f = x + y;
            unpack2(sp3, x, y); s3f = x + y;
        }
#pragma unroll
        for (int off = 1; off <= 8; off <<= 1) {
            s0f += __shfl_xor_sync(0xffffffffu, s0f, off);
            s1f += __shfl_xor_sync(0xffffffffu, s1f, off);
            s2f += __shfl_xor_sync(0xffffffffu, s2f, off);
            s3f += __shfl_xor_sync(0xffffffffu, s3f, off);
        }
        float p0 = ex2(s0f), p1 = ex2(s1f);
        float p2 = ex2(s2f), p3 = ex2(s3f);
        l[0] += p0; l[1] += p1; l[2] += p2; l[3] += p3;

        ULL pd0 = pack2(p0, p0), pd1 = pack2(p1, p1);
        ULL pd2 = pack2(p2, p2), pd3 = pack2(p3, p3);
#pragma unroll
        for (int j = 0; j < 4; j++) {
            acc[0][j] = ffma2(pd0, kp[j], acc[0][j]);
            acc[1][j] = ffma2(pd1, kp[j], acc[1][j]);
            acc[2][j] = ffma2(pd2, kp[j], acc[2][j]);
            acc[3][j] = ffma2(pd3, kp[j], acc[3][j]);
        }
    }

    // unpack natural pairs: a[h][0..3]=dims dl*4.., a[h][4..7]=dims 64+dl*4..
    float a[4][8];
#pragma unroll
    for (int h = 0; h < 4; h++) {
#pragma unroll
        for (int j = 0; j < 4; j++)
            unpack2(acc[h][j], a[h][2*j], a[h][2*j + 1]);
    }

    // merge the two rg halves (lane bit 4)
#pragma unroll
    for (int h = 0; h < 4; h++) {
        l[h] += __shfl_xor_sync(0xffffffffu, l[h], 16);
#pragma unroll
        for (int j = 0; j < 8; j++)
            a[h][j] += __shfl_xor_sync(0xffffffffu, a[h][j], 16);
    }

    __shared__ float sm_acc[4][REP][DH];
    __shared__ float sm_l[4][REP];
    if (rg == 0) {
#pragma unroll
        for (int h = 0; h < 4; h++) {
            *(float4*)&sm_acc[warp][h][dl * 4]      = make_float4(a[h][0], a[h][1], a[h][2], a[h][3]);
            *(float4*)&sm_acc[warp][h][64 + dl * 4] = make_float4(a[h][4], a[h][5], a[h][6], a[h][7]);
        }
    }
    if (lane == 0) {
#pragma unroll
        for (int h = 0; h < 4; h++) sm_l[warp][h] = l[h];
    }
    __syncthreads();

#pragma unroll
    for (int item = threadIdx.x; item < REP * DH; item += 128) {
        int h = item >> 7, d = item & (DH - 1);
        float O = sm_acc[0][h][d] + sm_acc[1][h][d] + sm_acc[2][h][d] + sm_acc[3][h][d];
        atomicAdd(&g_ao[b][(kv * REP + h) * DH + d], O);
    }
    if (threadIdx.x < REP) {
        float L = sm_l[0][threadIdx.x] + sm_l[1][threadIdx.x]
                + sm_l[2][threadIdx.x] + sm_l[3][threadIdx.x];
        atomicAdd(&g_l[b * HH + kv * REP + threadIdx.x], L);
    }
}

// ---------------- kernel 4: output projection (colpair, z=2, REDG to d_out) ----------------
// grid (8, 64, 2), block 128. Normalizes during smem fill; d_out pre-zeroed by rope.
__global__ void __launch_bounds__(128) proj_o_kernel(const float* __restrict__ wo,
                                                     float* __restrict__ out) {
    __shared__ ULL xs2[DCH][10];
    const int d0 = blockIdx.y * DCH;
    const int b0 = blockIdx.z * 8;
    {
        int i  = threadIdx.x;
        int b  = i / (DCH / 4);
        int d4 = i % (DCH / 4);
        float4 v = *(const float4*)(&g_ao[b0 + b][d0 + d4 * 4]);
        float inv = 1.f / g_l[(b0 + b) * HH + (d0 >> 7)];
        float vx = v.x * inv, vy = v.y * inv, vz = v.z * inv, vw = v.w * inv;
        xs2[d4 * 4 + 0][b] = pack2(vx, vx);
        xs2[d4 * 4 + 1][b] = pack2(vy, vy);
        xs2[d4 * 4 + 2][b] = pack2(vz, vz);
        xs2[d4 * 4 + 3][b] = pack2(vw, vw);
    }
    __syncthreads();

    const int col = (blockIdx.x * 128 + threadIdx.x) * 4;
    const float* w = wo + (size_t)d0 * DDIM + col;

    ULL acc[8][2];
#pragma unroll
    for (int b = 0; b < 8; b++) { acc[b][0] = 0ULL; acc[b][1] = 0ULL; }

    for (int dd = 0; dd < DCH; dd += 4) {
        float4 wv[4];
#pragma unroll
        for (int u = 0; u < 4; u++)
            wv[u] = *(const float4*)(w + (size_t)(dd + u) * DDIM);
#pragma unroll
        for (int u = 0; u < 4; u++) {
            ULL wA = ((const ULL*)&wv[u])[0];
            ULL wB = ((const ULL*)&wv[u])[1];
#pragma unroll
            for (int bp = 0; bp < 4; bp++) {
                ulonglong2 xv = *(const ulonglong2*)&xs2[dd + u][2 * bp];
                acc[2*bp    ][0] = ffma2(xv.x, wA, acc[2*bp    ][0]);
                acc[2*bp    ][1] = ffma2(xv.x, wB, acc[2*bp    ][1]);
                acc[2*bp + 1][0] = ffma2(xv.y, wA, acc[2*bp + 1][0]);
                acc[2*bp + 1][1] = ffma2(xv.y, wB, acc[2*bp + 1][1]);
            }
        }
    }

#pragma unroll
    for (int b = 0; b < 8; b++) {
        float c0, c1, c2, c3;
        unpack2(acc[b][0], c0, c1);
        unpack2(acc[b][1], c2, c3);
        float* op = out + (size_t)(b0 + b) * DDIM + col;
        atomicAdd(op + 0, c0);
        atomicAdd(op + 1, c1);
        atomicAdd(op + 2, c2);
        atomicAdd(op + 3, c3);
    }
}

// ---------------- launch ----------------
extern "C" void kernel_launch(void* const* d_in, const int* in_sizes, int n_in,
                              void* d_out, int out_size) {
    const float* x  = (const float*)d_in[0];
    const float* ck = (const float*)d_in[1];
    const float* wq = (const float*)d_in[3];
    const float* wk = (const float*)d_in[4];
    const float* wo = (const float*)d_in[6];
    const float* fc = (const float*)d_in[7];
    const float* fs = (const float*)d_in[8];
    float* out = (float*)d_out;

    proj_qk_kernel<<<dim3(QK_COLS / 512, NDCH, 2), 128>>>(x, wq, wk);
    rope_kernel<<<(BB * QK_COLS / 2 + 255) / 256, 256>>>(fc, fs, out);
    attn_kernel<<<dim3(BB * HKV, NSPLIT), 128>>>(ck);
    proj_o_kernel<<<dim3(DDIM / 512, NDCH, 2), 128>>>(wo, out);
}

// round 12
// speedup vs baseline: 1.0807x; 1.0807x over previous
#include <cuda_runtime.h>

#define BB 16
#define DDIM 4096
#define HH 32
#define HKV 8
#define DH 128
#define REP 4
#define LL 4096
#define QK_COLS (HH*DH + HKV*DH)   // 5120
#define NSPLIT 16
#define SPLIT_LEN (LL/NSPLIT)      // 256
#define NDCH 64
#define DCH (DDIM/NDCH)            // 64

typedef unsigned long long ULL;

// ---------------- scratch ----------------
__device__ float g_part_qk[NDCH][BB][QK_COLS];
__device__ float g_q[BB][HH][DH];         // roped q, pre-scaled by log2(e)/sqrt(128)
__device__ float g_knew[BB][HKV][DH];
__device__ float g_ao[BB][HH*DH];
__device__ float g_l[BB*HH];
__device__ float g_part_out[NDCH][BB][DDIM];

// ---------------- helpers ----------------
__device__ __forceinline__ ULL pack2(float lo, float hi) {
    ULL r;
    asm("mov.b64 %0, {%1, %2};" : "=l"(r) : "f"(lo), "f"(hi));
    return r;
}
__device__ __forceinline__ void unpack2(ULL v, float& lo, float& hi) {
    asm("mov.b64 {%0, %1}, %2;" : "=f"(lo), "=f"(hi) : "l"(v));
}
__device__ __forceinline__ ULL ffma2(ULL a, ULL b, ULL c) {
    ULL d;
    asm("fma.rn.f32x2 %0, %1, %2, %3;" : "=l"(d) : "l"(a), "l"(b), "l"(c));
    return d;
}
__device__ __forceinline__ float ex2(float x) {
    float r;
    asm("ex2.approx.f32 %0, %1;" : "=f"(r) : "f"(x));
    return r;
}

// ---------------- kernel 1: fused Q/K projection (colpair, z=2, STG partials) ----------------
// grid (10, 64, 2), block 128.
__global__ void __launch_bounds__(128) proj_qk_kernel(const float* __restrict__ x,
                                                      const float* __restrict__ wq,
                                                      const float* __restrict__ wk) {
    __shared__ ULL xs2[DCH][10];
    const int d0 = blockIdx.y * DCH;
    const int b0 = blockIdx.z * 8;

    {
        int i  = threadIdx.x;
        int b  = i / (DCH / 4);
        int d4 = i % (DCH / 4);
        float4 v = *(const float4*)(x + (size_t)(b0 + b) * DDIM + d0 + d4 * 4);
        xs2[d4 * 4 + 0][b] = pack2(v.x, v.x);
        xs2[d4 * 4 + 1][b] = pack2(v.y, v.y);
        xs2[d4 * 4 + 2][b] = pack2(v.z, v.z);
        xs2[d4 * 4 + 3][b] = pack2(v.w, v.w);
    }
    __syncthreads();

    const int col = (blockIdx.x * 128 + threadIdx.x) * 4;
    const float* w;
    int stride;
    if (col < HH * DH) { w = wq + col;              stride = HH * DH; }
    else               { w = wk + (col - HH * DH);  stride = HKV * DH; }
    w += (size_t)d0 * stride;

    ULL acc[8][2];
#pragma unroll
    for (int b = 0; b < 8; b++) { acc[b][0] = 0ULL; acc[b][1] = 0ULL; }

    for (int dd = 0; dd < DCH; dd += 4) {
        float4 wv[4];
#pragma unroll
        for (int u = 0; u < 4; u++)
            wv[u] = *(const float4*)(w + (size_t)(dd + u) * stride);
#pragma unroll
        for (int u = 0; u < 4; u++) {
            ULL wA = ((const ULL*)&wv[u])[0];
            ULL wB = ((const ULL*)&wv[u])[1];
#pragma unroll
            for (int bp = 0; bp < 4; bp++) {
                ulonglong2 xv = *(const ulonglong2*)&xs2[dd + u][2 * bp];
                acc[2*bp    ][0] = ffma2(xv.x, wA, acc[2*bp    ][0]);
                acc[2*bp    ][1] = ffma2(xv.x, wB, acc[2*bp    ][1]);
                acc[2*bp + 1][0] = ffma2(xv.y, wA, acc[2*bp + 1][0]);
                acc[2*bp + 1][1] = ffma2(xv.y, wB, acc[2*bp + 1][1]);
            }
        }
    }

#pragma unroll
    for (int b = 0; b < 8; b++) {
        float c0, c1, c2, c3;
        unpack2(acc[b][0], c0, c1);
        unpack2(acc[b][1], c2, c3);
        *(float4*)&g_part_qk[blockIdx.y][b0 + b][col] = make_float4(c0, c1, c2, c3);
    }
}

// ---------------- kernel 2: reduce chunks + RoPE; zero g_ao / g_l ----------------
__global__ void rope_kernel(const float* __restrict__ fc, const float* __restrict__ fs) {
    int idx = blockIdx.x * blockDim.x + threadIdx.x;
    const int TOT = BB * QK_COLS / 2;
    if (idx >= TOT) return;

    if (idx < BB * HH * DH / 2)
        *(float2*)&(((float*)g_ao)[idx * 2]) = make_float2(0.f, 0.f);
    if (idx < BB * HH) g_l[idx] = 0.f;

    int b   = idx / (QK_COLS / 2);
    int col = (idx % (QK_COLS / 2)) * 2;

    float e = 0.f, o = 0.f;
#pragma unroll
    for (int ch = 0; ch < NDCH; ch++) {
        float2 v = *(const float2*)&g_part_qk[ch][b][col];
        e += v.x; o += v.y;
    }
    int p = (col & (DH - 1)) >> 1;
    float c = fc[p], s = fs[p];
    float re = e * c - o * s;
    float ro = e * s + o * c;

    if (col < HH * DH) {
        const float sc = 0.1275174260809843f;   // log2(e)/sqrt(128): scores in log2 domain
        ((float*)g_q)[b * HH * DH + col]     = re * sc;
        ((float*)g_q)[b * HH * DH + col + 1] = ro * sc;
    } else {
        int kc = col - HH * DH;
        ((float*)g_knew)[b * HKV * DH + kc]     = re;
        ((float*)g_knew)[b * HKV * DH + kc + 1] = ro;
    }
}

// ---------------- kernel 3: flash-decode attention (V == K), no-max softmax ----------------
// grid (B*HKV, NSPLIT), block 256 (8 warps), occupancy 2.
// lane = (rg:bit4, hh:bit3, dl:bits0-2): rg = row of pair, hh = head-half (2 heads),
// dl = 16-dim slice. Butterfly over 8 dl-lanes only: 3 levels x 2 scores = 6 SHFL / 2 rows.
// K reads duplicated across hh halves hit identical addresses (coalescer dedups).
__global__ void __launch_bounds__(256, 2) attn_kernel(const float* __restrict__ cache_k) {
    const int b     = blockIdx.x / HKV;
    const int kv    = blockIdx.x % HKV;
    const int split = blockIdx.y;
    const int warp  = threadIdx.x >> 5;
    const int lane  = threadIdx.x & 31;
    const int rg    = lane >> 4;
    const int hh    = (lane >> 3) & 1;
    const int dl    = lane & 7;
    const int dbase = dl * 16;

    // q natural dim-pairs for this half's 2 heads: qd[t][j], t=head-in-half, j=pair 0..7
    ULL qd[2][8];
#pragma unroll
    for (int t = 0; t < 2; t++) {
        const float* qrow = &g_q[b][kv*REP + 2*hh + t][dbase];
#pragma unroll
        for (int j4 = 0; j4 < 4; j4++) {
            float4 v = *(const float4*)(qrow + j4 * 4);
            qd[t][2*j4    ] = ((const ULL*)&v)[0];
            qd[t][2*j4 + 1] = ((const ULL*)&v)[1];
        }
    }

    ULL acc[2][8];
#pragma unroll
    for (int t = 0; t < 2; t++)
#pragma unroll
        for (int j = 0; j < 8; j++) acc[t][j] = 0ULL;
    float l0 = 0.f, l1 = 0.f;

    const float* kbase = cache_k + (size_t)b * LL * (HKV * DH) + kv * DH + dbase;
    const float* knewp = &g_knew[b][kv][dbase];
    const int s0 = split * SPLIT_LEN + warp * (SPLIT_LEN / 8) + rg;

#pragma unroll 2
    for (int i = 0; i < SPLIT_LEN / 16; i++) {     // 16 iters, 2 rows each per warp
        int s = s0 + i * 2;
        const float* rp = (s == LL - 1) ? knewp : (kbase + (size_t)s * (HKV * DH));
        float4 k0 = *(const float4*)(rp);
        float4 k1 = *(const float4*)(rp + 4);
        float4 k2 = *(const float4*)(rp + 8);
        float4 k3 = *(const float4*)(rp + 12);
        ULL kp[8];
        kp[0] = ((const ULL*)&k0)[0]; kp[1] = ((const ULL*)&k0)[1];
        kp[2] = ((const ULL*)&k1)[0]; kp[3] = ((const ULL*)&k1)[1];
        kp[4] = ((const ULL*)&k2)[0]; kp[5] = ((const ULL*)&k2)[1];
        kp[6] = ((const ULL*)&k3)[0]; kp[7] = ((const ULL*)&k3)[1];

        // partial scores for the 2 heads of this half (log2 domain)
        ULL sp0 = 0ULL, sp1 = 0ULL;
#pragma unroll
        for (int j = 0; j < 8; j++) {
            sp0 = ffma2(qd[0][j], kp[j], sp0);
            sp1 = ffma2(qd[1][j], kp[j], sp1);
        }
        float s0f, s1f, xa, ya;
        unpack2(sp0, xa, ya); s0f = xa + ya;
        unpack2(sp1, xa, ya); s1f = xa + ya;

        // butterfly over 8 dl-lanes only: 3 levels
#pragma unroll
        for (int off = 1; off <= 4; off <<= 1) {
            s0f += __shfl_xor_sync(0xffffffffu, s0f, off);
            s1f += __shfl_xor_sync(0xffffffffu, s1f, off);
        }
        float p0 = ex2(s0f);
        float p1 = ex2(s1f);
        l0 += p0; l1 += p1;

        ULL pd0 = pack2(p0, p0);
        ULL pd1 = pack2(p1, p1);
#pragma unroll
        for (int j = 0; j < 8; j++) {
            acc[0][j] = ffma2(pd0, kp[j], acc[0][j]);
            acc[1][j] = ffma2(pd1, kp[j], acc[1][j]);
        }
    }

    // unpack accumulators
    float a[2][16];
#pragma unroll
    for (int t = 0; t < 2; t++)
#pragma unroll
        for (int j = 0; j < 8; j++)
            unpack2(acc[t][j], a[t][2*j], a[t][2*j + 1]);

    // merge the two rg halves (xor 16: partner has same hh, dl)
    l0 += __shfl_xor_sync(0xffffffffu, l0, 16);
    l1 += __shfl_xor_sync(0xffffffffu, l1, 16);
#pragma unroll
    for (int t = 0; t < 2; t++)
#pragma unroll
        for (int j = 0; j < 16; j++)
            a[t][j] += __shfl_xor_sync(0xffffffffu, a[t][j], 16);

    __shared__ float sm_acc[8][REP][DH];
    __shared__ float sm_l[8][REP];
    if (rg == 0) {
#pragma unroll
        for (int t = 0; t < 2; t++) {
            int h = 2 * hh + t;
#pragma unroll
            for (int j4 = 0; j4 < 4; j4++)
                *(float4*)&sm_acc[warp][h][dbase + j4 * 4] =
                    make_float4(a[t][4*j4], a[t][4*j4+1], a[t][4*j4+2], a[t][4*j4+3]);
        }
        if (dl == 0) {
            sm_l[warp][2 * hh    ] = l0;
            sm_l[warp][2 * hh + 1] = l1;
        }
    }
    __syncthreads();

    for (int item = threadIdx.x; item < REP * DH; item += 256) {
        int h = item >> 7, d = item & (DH - 1);
        float O = 0.f;
#pragma unroll
        for (int w = 0; w < 8; w++) O += sm_acc[w][h][d];
        atomicAdd(&g_ao[b][(kv * REP + h) * DH + d], O);
    }
    if (threadIdx.x < REP) {
        float L = 0.f;
#pragma unroll
        for (int w = 0; w < 8; w++) L += sm_l[w][threadIdx.x];
        atomicAdd(&g_l[b * HH + kv * REP + threadIdx.x], L);
    }
}

// ---------------- kernel 4: output projection (colpair, z=2, STG partials) ----------------
// grid (8, 64, 2), block 128. Normalizes during smem fill.
__global__ void __launch_bounds__(128) proj_o_kernel(const float* __restrict__ wo) {
    __shared__ ULL xs2[DCH][10];
    const int d0 = blockIdx.y * DCH;
    const int b0 = blockIdx.z * 8;
    {
        int i  = threadIdx.x;
        int b  = i / (DCH / 4);
        int d4 = i % (DCH / 4);
        float4 v = *(const float4*)(&g_ao[b0 + b][d0 + d4 * 4]);
        float inv = 1.f / g_l[(b0 + b) * HH + (d0 >> 7)];
        float vx = v.x * inv, vy = v.y * inv, vz = v.z * inv, vw = v.w * inv;
        xs2[d4 * 4 + 0][b] = pack2(vx, vx);
        xs2[d4 * 4 + 1][b] = pack2(vy, vy);
        xs2[d4 * 4 + 2][b] = pack2(vz, vz);
        xs2[d4 * 4 + 3][b] = pack2(vw, vw);
    }
    __syncthreads();

    const int col = (blockIdx.x * 128 + threadIdx.x) * 4;
    const float* w = wo + (size_t)d0 * DDIM + col;

    ULL acc[8][2];
#pragma unroll
    for (int b = 0; b < 8; b++) { acc[b][0] = 0ULL; acc[b][1] = 0ULL; }

    for (int dd = 0; dd < DCH; dd += 4) {
        float4 wv[4];
#pragma unroll
        for (int u = 0; u < 4; u++)
            wv[u] = *(const float4*)(w + (size_t)(dd + u) * DDIM);
#pragma unroll
        for (int u = 0; u < 4; u++) {
            ULL wA = ((const ULL*)&wv[u])[0];
            ULL wB = ((const ULL*)&wv[u])[1];
#pragma unroll
            for (int bp = 0; bp < 4; bp++) {
                ulonglong2 xv = *(const ulonglong2*)&xs2[dd + u][2 * bp];
                acc[2*bp    ][0] = ffma2(xv.x, wA, acc[2*bp    ][0]);
                acc[2*bp    ][1] = ffma2(xv.x, wB, acc[2*bp    ][1]);
                acc[2*bp + 1][0] = ffma2(xv.y, wA, acc[2*bp + 1][0]);
                acc[2*bp + 1][1] = ffma2(xv.y, wB, acc[2*bp + 1][1]);
            }
        }
    }

#pragma unroll
    for (int b = 0; b < 8; b++) {
        float c0, c1, c2, c3;
        unpack2(acc[b][0], c0, c1);
        unpack2(acc[b][1], c2, c3);
        *(float4*)&g_part_out[blockIdx.y][b0 + b][col] = make_float4(c0, c1, c2, c3);
    }
}

// ---------------- kernel 5: reduce output partials -> d_out (float4) ----------------
__global__ void __launch_bounds__(128) reduce_out_kernel(float* __restrict__ out) {
    int idx = blockIdx.x * 128 + threadIdx.x;
    int b  = idx >> 10;
    int c4 = (idx & 1023) << 2;
    float4 s = make_float4(0.f, 0.f, 0.f, 0.f);
#pragma unroll
    for (int ch = 0; ch < NDCH; ch++) {
        float4 v = *(const float4*)&g_part_out[ch][b][c4];
        s.x += v.x; s.y += v.y; s.z += v.z; s.w += v.w;
    }
    *(float4*)&out[b * DDIM + c4] = s;
}

// ---------------- launch ----------------
extern "C" void kernel_launch(void* const* d_in, const int* in_sizes, int n_in,
                              void* d_out, int out_size) {
    const float* x  = (const float*)d_in[0];
    const float* ck = (const float*)d_in[1];
    const float* wq = (const float*)d_in[3];
    const float* wk = (const float*)d_in[4];
    const float* wo = (const float*)d_in[6];
    const float* fc = (const float*)d_in[7];
    const float* fs = (const float*)d_in[8];

    proj_qk_kernel<<<dim3(QK_COLS / 512, NDCH, 2), 128>>>(x, wq, wk);
    rope_kernel<<<(BB * QK_COLS / 2 + 255) / 256, 256>>>(fc, fs);
    attn_kernel<<<dim3(BB * HKV, NSPLIT), 256>>>(ck);
    proj_o_kernel<<<dim3(DDIM / 512, NDCH, 2), 128>>>(wo);
    reduce_out_kernel<<<(BB * DDIM / 4) / 128, 128>>>((float*)d_out);
}

// round 13
// speedup vs baseline: 1.2263x; 1.1347x over previous
#include <cuda_runtime.h>

#define BB 16
#define DDIM 4096
#define HH 32
#define HKV 8
#define DH 128
#define REP 4
#define LL 4096
#define QK_COLS (HH*DH + HKV*DH)   // 5120
#define NSPLIT 16
#define SPLIT_LEN (LL/NSPLIT)      // 256
#define NDCH 64
#define DCH (DDIM/NDCH)            // 64

typedef unsigned long long ULL;

// ---------------- scratch ----------------
__device__ float g_part_qk[NDCH][BB][QK_COLS];
__device__ float g_q[BB][HH][DH];         // roped q, pre-scaled by log2(e)/sqrt(128)
__device__ float g_knew[BB][HKV][DH];
__device__ float g_ao[BB][HH*DH];
__device__ float g_l[BB*HH];
__device__ float g_part_out[NDCH][BB][DDIM];

// ---------------- helpers ----------------
__device__ __forceinline__ ULL pack2(float lo, float hi) {
    ULL r;
    asm("mov.b64 %0, {%1, %2};" : "=l"(r) : "f"(lo), "f"(hi));
    return r;
}
__device__ __forceinline__ void unpack2(ULL v, float& lo, float& hi) {
    asm("mov.b64 {%0, %1}, %2;" : "=f"(lo), "=f"(hi) : "l"(v));
}
__device__ __forceinline__ ULL ffma2(ULL a, ULL b, ULL c) {
    ULL d;
    asm("fma.rn.f32x2 %0, %1, %2, %3;" : "=l"(d) : "l"(a), "l"(b), "l"(c));
    return d;
}
__device__ __forceinline__ ULL add2(ULL a, ULL b) {
    ULL d;
    asm("add.rn.f32x2 %0, %1, %2;" : "=l"(d) : "l"(a), "l"(b));
    return d;
}
__device__ __forceinline__ float ex2(float x) {
    float r;
    asm("ex2.approx.f32 %0, %1;" : "=f"(r) : "f"(x));
    return r;
}

// ---------------- kernel 1: fused Q/K projection (colpair, z=2, STG partials) ----------------
// grid (10, 64, 2), block 128.
__global__ void __launch_bounds__(128) proj_qk_kernel(const float* __restrict__ x,
                                                      const float* __restrict__ wq,
                                                      const float* __restrict__ wk) {
    __shared__ ULL xs2[DCH][10];
    const int d0 = blockIdx.y * DCH;
    const int b0 = blockIdx.z * 8;

    {
        int i  = threadIdx.x;
        int b  = i / (DCH / 4);
        int d4 = i % (DCH / 4);
        float4 v = *(const float4*)(x + (size_t)(b0 + b) * DDIM + d0 + d4 * 4);
        xs2[d4 * 4 + 0][b] = pack2(v.x, v.x);
        xs2[d4 * 4 + 1][b] = pack2(v.y, v.y);
        xs2[d4 * 4 + 2][b] = pack2(v.z, v.z);
        xs2[d4 * 4 + 3][b] = pack2(v.w, v.w);
    }
    __syncthreads();

    const int col = (blockIdx.x * 128 + threadIdx.x) * 4;
    const float* w;
    int stride;
    if (col < HH * DH) { w = wq + col;              stride = HH * DH; }
    else               { w = wk + (col - HH * DH);  stride = HKV * DH; }
    w += (size_t)d0 * stride;

    ULL acc[8][2];
#pragma unroll
    for (int b = 0; b < 8; b++) { acc[b][0] = 0ULL; acc[b][1] = 0ULL; }

    for (int dd = 0; dd < DCH; dd += 4) {
        float4 wv[4];
#pragma unroll
        for (int u = 0; u < 4; u++)
            wv[u] = *(const float4*)(w + (size_t)(dd + u) * stride);
#pragma unroll
        for (int u = 0; u < 4; u++) {
            ULL wA = ((const ULL*)&wv[u])[0];
            ULL wB = ((const ULL*)&wv[u])[1];
#pragma unroll
            for (int bp = 0; bp < 4; bp++) {
                ulonglong2 xv = *(const ulonglong2*)&xs2[dd + u][2 * bp];
                acc[2*bp    ][0] = ffma2(xv.x, wA, acc[2*bp    ][0]);
                acc[2*bp    ][1] = ffma2(xv.x, wB, acc[2*bp    ][1]);
                acc[2*bp + 1][0] = ffma2(xv.y, wA, acc[2*bp + 1][0]);
                acc[2*bp + 1][1] = ffma2(xv.y, wB, acc[2*bp + 1][1]);
            }
        }
    }

#pragma unroll
    for (int b = 0; b < 8; b++) {
        float c0, c1, c2, c3;
        unpack2(acc[b][0], c0, c1);
        unpack2(acc[b][1], c2, c3);
        *(float4*)&g_part_qk[blockIdx.y][b0 + b][col] = make_float4(c0, c1, c2, c3);
    }
}

// ---------------- kernel 2: reduce chunks + RoPE; zero g_ao / g_l ----------------
__global__ void rope_kernel(const float* __restrict__ fc, const float* __restrict__ fs) {
    int idx = blockIdx.x * blockDim.x + threadIdx.x;
    const int TOT = BB * QK_COLS / 2;
    if (idx >= TOT) return;

    if (idx < BB * HH * DH / 2)
        *(float2*)&(((float*)g_ao)[idx * 2]) = make_float2(0.f, 0.f);
    if (idx < BB * HH) g_l[idx] = 0.f;

    int b   = idx / (QK_COLS / 2);
    int col = (idx % (QK_COLS / 2)) * 2;

    float e = 0.f, o = 0.f;
#pragma unroll
    for (int ch = 0; ch < NDCH; ch++) {
        float2 v = *(const float2*)&g_part_qk[ch][b][col];
        e += v.x; o += v.y;
    }
    int p = (col & (DH - 1)) >> 1;
    float c = fc[p], s = fs[p];
    float re = e * c - o * s;
    float ro = e * s + o * c;

    if (col < HH * DH) {
        const float sc = 0.1275174260809843f;   // log2(e)/sqrt(128): scores in log2 domain
        ((float*)g_q)[b * HH * DH + col]     = re * sc;
        ((float*)g_q)[b * HH * DH + col + 1] = ro * sc;
    } else {
        int kc = col - HH * DH;
        ((float*)g_knew)[b * HKV * DH + kc]     = re;
        ((float*)g_knew)[b * HKV * DH + kc + 1] = ro;
    }
}

// ---------------- kernel 3: flash-decode attention (V == K), no-max softmax ----------------
// grid (B*HKV, NSPLIT), block 256 (8 warps), occupancy 2. [R8 geometry, ex2 scores]
__global__ void __launch_bounds__(256, 2) attn_kernel(const float* __restrict__ cache_k) {
    const int b     = blockIdx.x / HKV;
    const int kv    = blockIdx.x % HKV;
    const int split = blockIdx.y;
    const int warp  = threadIdx.x >> 5;
    const int lane  = threadIdx.x & 31;
    const int rg    = lane >> 4;
    const int dl    = lane & 15;

    ULL qp0[2][4], qp1[2][4];
#pragma unroll
    for (int hp = 0; hp < 2; hp++) {
        float4 a0 = *(const float4*)&g_q[b][kv*REP + 2*hp    ][dl * 4];
        float4 b0 = *(const float4*)&g_q[b][kv*REP + 2*hp + 1][dl * 4];
        float4 a1 = *(const float4*)&g_q[b][kv*REP + 2*hp    ][64 + dl * 4];
        float4 b1 = *(const float4*)&g_q[b][kv*REP + 2*hp + 1][64 + dl * 4];
        qp0[hp][0] = pack2(a0.x, b0.x); qp0[hp][1] = pack2(a0.y, b0.y);
        qp0[hp][2] = pack2(a0.z, b0.z); qp0[hp][3] = pack2(a0.w, b0.w);
        qp1[hp][0] = pack2(a1.x, b1.x); qp1[hp][1] = pack2(a1.y, b1.y);
        qp1[hp][2] = pack2(a1.z, b1.z); qp1[hp][3] = pack2(a1.w, b1.w);
    }

    ULL acc0[2][4], acc1[2][4];
#pragma unroll
    for (int hp = 0; hp < 2; hp++)
#pragma unroll
        for (int j = 0; j < 4; j++) { acc0[hp][j] = 0ULL; acc1[hp][j] = 0ULL; }
    ULL l2a = 0ULL, l2b = 0ULL;

    const float* kbase = cache_k + (size_t)b * LL * (HKV * DH) + kv * DH;
    const float* knewp = &g_knew[b][kv][0];
    const int s0 = split * SPLIT_LEN + warp * (SPLIT_LEN / 8) + rg;

#pragma unroll 2
    for (int i = 0; i < SPLIT_LEN / 16; i++) {
        int s = s0 + i * 2;
        const float* rp = (s == LL - 1) ? knewp : (kbase + (size_t)s * (HKV * DH));
        float4 k0 = *(const float4*)(rp + dl * 4);
        float4 k1 = *(const float4*)(rp + 64 + dl * 4);

        ULL kd[8];
        kd[0] = pack2(k0.x, k0.x); kd[1] = pack2(k0.y, k0.y);
        kd[2] = pack2(k0.z, k0.z); kd[3] = pack2(k0.w, k0.w);
        kd[4] = pack2(k1.x, k1.x); kd[5] = pack2(k1.y, k1.y);
        kd[6] = pack2(k1.z, k1.z); kd[7] = pack2(k1.w, k1.w);

        ULL sa = 0ULL, sb = 0ULL;
#pragma unroll
        for (int j = 0; j < 4; j++) {
            sa = ffma2(qp0[0][j], kd[j], sa);
            sb = ffma2(qp0[1][j], kd[j], sb);
            sa = ffma2(qp1[0][j], kd[4 + j], sa);
            sb = ffma2(qp1[1][j], kd[4 + j], sb);
        }
        float s0f, s1f, s2f, s3f;
        unpack2(sa, s0f, s1f);
        unpack2(sb, s2f, s3f);
#pragma unroll
        for (int off = 1; off <= 8; off <<= 1) {
            s0f += __shfl_xor_sync(0xffffffffu, s0f, off);
            s1f += __shfl_xor_sync(0xffffffffu, s1f, off);
            s2f += __shfl_xor_sync(0xffffffffu, s2f, off);
            s3f += __shfl_xor_sync(0xffffffffu, s3f, off);
        }
        float p0 = ex2(s0f), p1 = ex2(s1f);
        float p2 = ex2(s2f), p3 = ex2(s3f);
        ULL pp0 = pack2(p0, p1);
        ULL pp1 = pack2(p2, p3);
        l2a = add2(l2a, pp0);
        l2b = add2(l2b, pp1);
#pragma unroll
        for (int j = 0; j < 4; j++) {
            acc0[0][j] = ffma2(pp0, kd[j],     acc0[0][j]);
            acc0[1][j] = ffma2(pp1, kd[j],     acc0[1][j]);
            acc1[0][j] = ffma2(pp0, kd[4 + j], acc1[0][j]);
            acc1[1][j] = ffma2(pp1, kd[4 + j], acc1[1][j]);
        }
    }

    float a[4][8], l[4];
#pragma unroll
    for (int j = 0; j < 4; j++) {
        unpack2(acc0[0][j], a[0][j], a[1][j]);
        unpack2(acc0[1][j], a[2][j], a[3][j]);
        unpack2(acc1[0][j], a[0][4 + j], a[1][4 + j]);
        unpack2(acc1[1][j], a[2][4 + j], a[3][4 + j]);
    }
    unpack2(l2a, l[0], l[1]);
    unpack2(l2b, l[2], l[3]);

#pragma unroll
    for (int h = 0; h < 4; h++) {
        l[h] += __shfl_xor_sync(0xffffffffu, l[h], 16);
#pragma unroll
        for (int j = 0; j < 8; j++)
            a[h][j] += __shfl_xor_sync(0xffffffffu, a[h][j], 16);
    }

    __shared__ float sm_acc[8][REP][DH];
    __shared__ float sm_l[8][REP];
    if (rg == 0) {
#pragma unroll
        for (int h = 0; h < 4; h++) {
            *(float4*)&sm_acc[warp][h][dl * 4]      = make_float4(a[h][0], a[h][1], a[h][2], a[h][3]);
            *(float4*)&sm_acc[warp][h][64 + dl * 4] = make_float4(a[h][4], a[h][5], a[h][6], a[h][7]);
        }
    }
    if (lane == 0) {
#pragma unroll
        for (int h = 0; h < 4; h++) sm_l[warp][h] = l[h];
    }
    __syncthreads();

    for (int item = threadIdx.x; item < REP * DH; item += 256) {
        int h = item >> 7, d = item & (DH - 1);
        float O = 0.f;
#pragma unroll
        for (int w = 0; w < 8; w++) O += sm_acc[w][h][d];
        atomicAdd(&g_ao[b][(kv * REP + h) * DH + d], O);
    }
    if (threadIdx.x < REP) {
        float L = 0.f;
#pragma unroll
        for (int w = 0; w < 8; w++) L += sm_l[w][threadIdx.x];
        atomicAdd(&g_l[b * HH + kv * REP + threadIdx.x], L);
    }
}

// ---------------- kernel 4: output projection (colpair, z=2, STG partials) ----------------
// grid (8, 64, 2), block 128. Normalizes during smem fill.
__global__ void __launch_bounds__(128) proj_o_kernel(const float* __restrict__ wo) {
    __shared__ ULL xs2[DCH][10];
    const int d0 = blockIdx.y * DCH;
    const int b0 = blockIdx.z * 8;
    {
        int i  = threadIdx.x;
        int b  = i / (DCH / 4);
        int d4 = i % (DCH / 4);
        float4 v = *(const float4*)(&g_ao[b0 + b][d0 + d4 * 4]);
        float inv = 1.f / g_l[(b0 + b) * HH + (d0 >> 7)];
        float vx = v.x * inv, vy = v.y * inv, vz = v.z * inv, vw = v.w * inv;
        xs2[d4 * 4 + 0][b] = pack2(vx, vx);
        xs2[d4 * 4 + 1][b] = pack2(vy, vy);
        xs2[d4 * 4 + 2][b] = pack2(vz, vz);
        xs2[d4 * 4 + 3][b] = pack2(vw, vw);
    }
    __syncthreads();

    const int col = (blockIdx.x * 128 + threadIdx.x) * 4;
    const float* w = wo + (size_t)d0 * DDIM + col;

    ULL acc[8][2];
#pragma unroll
    for (int b = 0; b < 8; b++) { acc[b][0] = 0ULL; acc[b][1] = 0ULL; }

    for (int dd = 0; dd < DCH; dd += 4) {
        float4 wv[4];
#pragma unroll
        for (int u = 0; u < 4; u++)
            wv[u] = *(const float4*)(w + (size_t)(dd + u) * DDIM);
#pragma unroll
        for (int u = 0; u < 4; u++) {
            ULL wA = ((const ULL*)&wv[u])[0];
            ULL wB = ((const ULL*)&wv[u])[1];
#pragma unroll
            for (int bp = 0; bp < 4; bp++) {
                ulonglong2 xv = *(const ulonglong2*)&xs2[dd + u][2 * bp];
                acc[2*bp    ][0] = ffma2(xv.x, wA, acc[2*bp    ][0]);
                acc[2*bp    ][1] = ffma2(xv.x, wB, acc[2*bp    ][1]);
                acc[2*bp + 1][0] = ffma2(xv.y, wA, acc[2*bp + 1][0]);
                acc[2*bp + 1][1] = ffma2(xv.y, wB, acc[2*bp + 1][1]);
            }
        }
    }

#pragma unroll
    for (int b = 0; b < 8; b++) {
        float c0, c1, c2, c3;
        unpack2(acc[b][0], c0, c1);
        unpack2(acc[b][1], c2, c3);
        *(float4*)&g_part_out[blockIdx.y][b0 + b][col] = make_float4(c0, c1, c2, c3);
    }
}

// ---------------- kernel 5: reduce output partials -> d_out (float4) ----------------
__global__ void __launch_bounds__(128) reduce_out_kernel(float* __restrict__ out) {
    int idx = blockIdx.x * 128 + threadIdx.x;
    int b  = idx >> 10;
    int c4 = (idx & 1023) << 2;
    float4 s = make_float4(0.f, 0.f, 0.f, 0.f);
#pragma unroll
    for (int ch = 0; ch < NDCH; ch++) {
        float4 v = *(const float4*)&g_part_out[ch][b][c4];
        s.x += v.x; s.y += v.y; s.z += v.z; s.w += v.w;
    }
    *(float4*)&out[b * DDIM + c4] = s;
}

// ---------------- launch ----------------
extern "C" void kernel_launch(void* const* d_in, const int* in_sizes, int n_in,
                              void* d_out, int out_size) {
    const float* x  = (const float*)d_in[0];
    const float* ck = (const float*)d_in[1];
    const float* wq = (const float*)d_in[3];
    const float* wk = (const float*)d_in[4];
    const float* wo = (const float*)d_in[6];
    const float* fc = (const float*)d_in[7];
    const float* fs = (const float*)d_in[8];

    proj_qk_kernel<<<dim3(QK_COLS / 512, NDCH, 2), 128>>>(x, wq, wk);
    rope_kernel<<<(BB * QK_COLS / 2 + 255) / 256, 256>>>(fc, fs);
    attn_kernel<<<dim3(BB * HKV, NSPLIT), 256>>>(ck);
    proj_o_kernel<<<dim3(DDIM / 512, NDCH, 2), 128>>>(wo);
    reduce_out_kernel<<<(BB * DDIM / 4) / 128, 128>>>((float*)d_out);
}

// round 14
// speedup vs baseline: 1.3552x; 1.1051x over previous
#include <cuda_runtime.h>

#define BB 16
#define DDIM 4096
#define HH 32
#define HKV 8
#define DH 128
#define REP 4
#define LL 4096
#define QK_COLS (HH*DH + HKV*DH)   // 5120
#define NSPLIT 16
#define SPLIT_LEN (LL/NSPLIT)      // 256
#define NDCH 64
#define DCH (DDIM/NDCH)            // 64

typedef unsigned long long ULL;

// ---------------- scratch ----------------
__device__ float g_part_qk[NDCH][BB][QK_COLS];
__device__ float g_q[BB][HH][DH];         // roped q, pre-scaled by log2(e)/sqrt(128)
__device__ float g_knew[BB][HKV][DH];
__device__ float g_ao[BB][HH*DH];
__device__ float g_l[BB*HH];
__device__ float g_part_out[NDCH][BB][DDIM];

// ---------------- helpers ----------------
__device__ __forceinline__ ULL pack2(float lo, float hi) {
    ULL r;
    asm("mov.b64 %0, {%1, %2};" : "=l"(r) : "f"(lo), "f"(hi));
    return r;
}
__device__ __forceinline__ void unpack2(ULL v, float& lo, float& hi) {
    asm("mov.b64 {%0, %1}, %2;" : "=f"(lo), "=f"(hi) : "l"(v));
}
__device__ __forceinline__ ULL ffma2(ULL a, ULL b, ULL c) {
    ULL d;
    asm("fma.rn.f32x2 %0, %1, %2, %3;" : "=l"(d) : "l"(a), "l"(b), "l"(c));
    return d;
}
__device__ __forceinline__ ULL add2(ULL a, ULL b) {
    ULL d;
    asm("add.rn.f32x2 %0, %1, %2;" : "=l"(d) : "l"(a), "l"(b));
    return d;
}
__device__ __forceinline__ float ex2(float x) {
    float r;
    asm("ex2.approx.f32 %0, %1;" : "=f"(r) : "f"(x));
    return r;
}

// ---------------- kernel 1: fused Q/K projection (colpair, z=2, STG partials) ----------------
// grid (10, 64, 2), block 128.
__global__ void __launch_bounds__(128) proj_qk_kernel(const float* __restrict__ x,
                                                      const float* __restrict__ wq,
                                                      const float* __restrict__ wk) {
    __shared__ ULL xs2[DCH][10];
    const int d0 = blockIdx.y * DCH;
    const int b0 = blockIdx.z * 8;

    {
        int i  = threadIdx.x;
        int b  = i / (DCH / 4);
        int d4 = i % (DCH / 4);
        float4 v = *(const float4*)(x + (size_t)(b0 + b) * DDIM + d0 + d4 * 4);
        xs2[d4 * 4 + 0][b] = pack2(v.x, v.x);
        xs2[d4 * 4 + 1][b] = pack2(v.y, v.y);
        xs2[d4 * 4 + 2][b] = pack2(v.z, v.z);
        xs2[d4 * 4 + 3][b] = pack2(v.w, v.w);
    }
    __syncthreads();

    const int col = (blockIdx.x * 128 + threadIdx.x) * 4;
    const float* w;
    int stride;
    if (col < HH * DH) { w = wq + col;              stride = HH * DH; }
    else               { w = wk + (col - HH * DH);  stride = HKV * DH; }
    w += (size_t)d0 * stride;

    ULL acc[8][2];
#pragma unroll
    for (int b = 0; b < 8; b++) { acc[b][0] = 0ULL; acc[b][1] = 0ULL; }

    for (int dd = 0; dd < DCH; dd += 4) {
        float4 wv[4];
#pragma unroll
        for (int u = 0; u < 4; u++)
            wv[u] = *(const float4*)(w + (size_t)(dd + u) * stride);
#pragma unroll
        for (int u = 0; u < 4; u++) {
            ULL wA = ((const ULL*)&wv[u])[0];
            ULL wB = ((const ULL*)&wv[u])[1];
#pragma unroll
            for (int bp = 0; bp < 4; bp++) {
                ulonglong2 xv = *(const ulonglong2*)&xs2[dd + u][2 * bp];
                acc[2*bp    ][0] = ffma2(xv.x, wA, acc[2*bp    ][0]);
                acc[2*bp    ][1] = ffma2(xv.x, wB, acc[2*bp    ][1]);
                acc[2*bp + 1][0] = ffma2(xv.y, wA, acc[2*bp + 1][0]);
                acc[2*bp + 1][1] = ffma2(xv.y, wB, acc[2*bp + 1][1]);
            }
        }
    }

#pragma unroll
    for (int b = 0; b < 8; b++) {
        float c0, c1, c2, c3;
        unpack2(acc[b][0], c0, c1);
        unpack2(acc[b][1], c2, c3);
        *(float4*)&g_part_qk[blockIdx.y][b0 + b][col] = make_float4(c0, c1, c2, c3);
    }
}

// ---------------- kernel 2: reduce chunks + RoPE; zero g_ao / g_l ----------------
__global__ void rope_kernel(const float* __restrict__ fc, const float* __restrict__ fs) {
    int idx = blockIdx.x * blockDim.x + threadIdx.x;
    const int TOT = BB * QK_COLS / 2;
    if (idx >= TOT) return;

    if (idx < BB * HH * DH / 2)
        *(float2*)&(((float*)g_ao)[idx * 2]) = make_float2(0.f, 0.f);
    if (idx < BB * HH) g_l[idx] = 0.f;

    int b   = idx / (QK_COLS / 2);
    int col = (idx % (QK_COLS / 2)) * 2;

    float e = 0.f, o = 0.f;
#pragma unroll
    for (int ch = 0; ch < NDCH; ch++) {
        float2 v = *(const float2*)&g_part_qk[ch][b][col];
        e += v.x; o += v.y;
    }
    int p = (col & (DH - 1)) >> 1;
    float c = fc[p], s = fs[p];
    float re = e * c - o * s;
    float ro = e * s + o * c;

    if (col < HH * DH) {
        const float sc = 0.1275174260809843f;   // log2(e)/sqrt(128): scores in log2 domain
        ((float*)g_q)[b * HH * DH + col]     = re * sc;
        ((float*)g_q)[b * HH * DH + col + 1] = ro * sc;
    } else {
        int kc = col - HH * DH;
        ((float*)g_knew)[b * HKV * DH + kc]     = re;
        ((float*)g_knew)[b * HKV * DH + kc + 1] = ro;
    }
}

// ---------------- kernel 3: flash-decode attention (V == K), no-max softmax ----------------
// grid (B*HKV, NSPLIT), block 256 (8 warps), occupancy 2.
// cp.async 2-stage x 4-row per-warp pipeline stages K into smem (depth decoupled
// from registers); compute body = R8 geometry (rg/dl) with ex2 log2-domain scores.
// Stage smem (32KB) is reused as the merge buffer after the main loop.
__global__ void __launch_bounds__(256, 2) attn_kernel(const float* __restrict__ cache_k) {
    const int b     = blockIdx.x / HKV;
    const int kv    = blockIdx.x % HKV;
    const int split = blockIdx.y;
    const int warp  = threadIdx.x >> 5;
    const int lane  = threadIdx.x & 31;
    const int rg    = lane >> 4;
    const int dl    = lane & 15;

    __shared__ float st[8][2][4][DH];     // 32KB staging; aliased as sm_acc later
    __shared__ float sm_l[8][REP];

    ULL qp0[2][4], qp1[2][4];
#pragma unroll
    for (int hp = 0; hp < 2; hp++) {
        float4 a0 = *(const float4*)&g_q[b][kv*REP + 2*hp    ][dl * 4];
        float4 b0 = *(const float4*)&g_q[b][kv*REP + 2*hp + 1][dl * 4];
        float4 a1 = *(const float4*)&g_q[b][kv*REP + 2*hp    ][64 + dl * 4];
        float4 b1 = *(const float4*)&g_q[b][kv*REP + 2*hp + 1][64 + dl * 4];
        qp0[hp][0] = pack2(a0.x, b0.x); qp0[hp][1] = pack2(a0.y, b0.y);
        qp0[hp][2] = pack2(a0.z, b0.z); qp0[hp][3] = pack2(a0.w, b0.w);
        qp1[hp][0] = pack2(a1.x, b1.x); qp1[hp][1] = pack2(a1.y, b1.y);
        qp1[hp][2] = pack2(a1.z, b1.z); qp1[hp][3] = pack2(a1.w, b1.w);
    }

    ULL acc0[2][4], acc1[2][4];
#pragma unroll
    for (int hp = 0; hp < 2; hp++)
#pragma unroll
        for (int j = 0; j < 4; j++) { acc0[hp][j] = 0ULL; acc1[hp][j] = 0ULL; }
    ULL l2a = 0ULL, l2b = 0ULL;

    const float* kbase = cache_k + (size_t)b * LL * (HKV * DH) + kv * DH;
    const float* knewp = &g_knew[b][kv][0];
    const int sbase = split * SPLIT_LEN + warp * 32;

    // staging lane roles: r_ld = row within stage (0..3), coff = 16B chunk offset
    const int r_ld = lane >> 3;
    const int coff = (lane & 7) * 16;
    const unsigned stb = (unsigned)__cvta_generic_to_shared(&st[warp][0][0][0]);

#define LOAD_STAGE(BUF, S0)                                                        \
    {                                                                              \
        int s_ = (S0) + r_ld;                                                      \
        const char* src_ = (const char*)((s_ == LL - 1) ? knewp                    \
                              : (kbase + (size_t)s_ * (HKV * DH)));                \
        unsigned dst_ = stb + (BUF) * 2048 + r_ld * 512 + coff;                    \
        _Pragma("unroll")                                                          \
        for (int c_ = 0; c_ < 4; c_++)                                             \
            asm volatile("cp.async.cg.shared.global [%0], [%1], 16;"               \
                         :: "r"(dst_ + c_ * 128), "l"(src_ + coff + c_ * 128)      \
                         : "memory");                                              \
    }

    LOAD_STAGE(0, sbase)
    asm volatile("cp.async.commit_group;" ::: "memory");
    LOAD_STAGE(1, sbase + 4)
    asm volatile("cp.async.commit_group;" ::: "memory");

    for (int g = 0; g < 8; g++) {
        asm volatile("cp.async.wait_group 1;" ::: "memory");
        __syncwarp();
        const float* bufp = &st[warp][g & 1][0][0];
#pragma unroll
        for (int it = 0; it < 2; it++) {
            const float* rp = bufp + (it * 2 + rg) * DH;
            float4 k0 = *(const float4*)(rp + dl * 4);
            float4 k1 = *(const float4*)(rp + 64 + dl * 4);

            ULL kd[8];
            kd[0] = pack2(k0.x, k0.x); kd[1] = pack2(k0.y, k0.y);
            kd[2] = pack2(k0.z, k0.z); kd[3] = pack2(k0.w, k0.w);
            kd[4] = pack2(k1.x, k1.x); kd[5] = pack2(k1.y, k1.y);
            kd[6] = pack2(k1.z, k1.z); kd[7] = pack2(k1.w, k1.w);

            ULL sa = 0ULL, sb = 0ULL;
#pragma unroll
            for (int j = 0; j < 4; j++) {
                sa = ffma2(qp0[0][j], kd[j], sa);
                sb = ffma2(qp0[1][j], kd[j], sb);
                sa = ffma2(qp1[0][j], kd[4 + j], sa);
                sb = ffma2(qp1[1][j], kd[4 + j], sb);
            }
            float s0f, s1f, s2f, s3f;
            unpack2(sa, s0f, s1f);
            unpack2(sb, s2f, s3f);
#pragma unroll
            for (int off = 1; off <= 8; off <<= 1) {
                s0f += __shfl_xor_sync(0xffffffffu, s0f, off);
                s1f += __shfl_xor_sync(0xffffffffu, s1f, off);
                s2f += __shfl_xor_sync(0xffffffffu, s2f, off);
                s3f += __shfl_xor_sync(0xffffffffu, s3f, off);
            }
            float p0 = ex2(s0f), p1 = ex2(s1f);
            float p2 = ex2(s2f), p3 = ex2(s3f);
            ULL pp0 = pack2(p0, p1);
            ULL pp1 = pack2(p2, p3);
            l2a = add2(l2a, pp0);
            l2b = add2(l2b, pp1);
#pragma unroll
            for (int j = 0; j < 4; j++) {
                acc0[0][j] = ffma2(pp0, kd[j],     acc0[0][j]);
                acc0[1][j] = ffma2(pp1, kd[j],     acc0[1][j]);
                acc1[0][j] = ffma2(pp0, kd[4 + j], acc1[0][j]);
                acc1[1][j] = ffma2(pp1, kd[4 + j], acc1[1][j]);
            }
        }
        __syncwarp();   // all lanes done reading this buffer before refilling it
        if (g < 6) LOAD_STAGE(g & 1, sbase + (g + 2) * 4)
        asm volatile("cp.async.commit_group;" ::: "memory");
    }
#undef LOAD_STAGE

    float a[4][8], l[4];
#pragma unroll
    for (int j = 0; j < 4; j++) {
        unpack2(acc0[0][j], a[0][j], a[1][j]);
        unpack2(acc0[1][j], a[2][j], a[3][j]);
        unpack2(acc1[0][j], a[0][4 + j], a[1][4 + j]);
        unpack2(acc1[1][j], a[2][4 + j], a[3][4 + j]);
    }
    unpack2(l2a, l[0], l[1]);
    unpack2(l2b, l[2], l[3]);

#pragma unroll
    for (int h = 0; h < 4; h++) {
        l[h] += __shfl_xor_sync(0xffffffffu, l[h], 16);
#pragma unroll
        for (int j = 0; j < 8; j++)
            a[h][j] += __shfl_xor_sync(0xffffffffu, a[h][j], 16);
    }

    __syncthreads();    // all warps done with staging smem — safe to alias
    float (*sm_acc)[REP][DH] = (float (*)[REP][DH])st;
    if (rg == 0) {
#pragma unroll
        for (int h = 0; h < 4; h++) {
            *(float4*)&sm_acc[warp][h][dl * 4]      = make_float4(a[h][0], a[h][1], a[h][2], a[h][3]);
            *(float4*)&sm_acc[warp][h][64 + dl * 4] = make_float4(a[h][4], a[h][5], a[h][6], a[h][7]);
        }
    }
    if (lane == 0) {
#pragma unroll
        for (int h = 0; h < 4; h++) sm_l[warp][h] = l[h];
    }
    __syncthreads();

    for (int item = threadIdx.x; item < REP * DH; item += 256) {
        int h = item >> 7, d = item & (DH - 1);
        float O = 0.f;
#pragma unroll
        for (int w = 0; w < 8; w++) O += sm_acc[w][h][d];
        atomicAdd(&g_ao[b][(kv * REP + h) * DH + d], O);
    }
    if (threadIdx.x < REP) {
        float L = 0.f;
#pragma unroll
        for (int w = 0; w < 8; w++) L += sm_l[w][threadIdx.x];
        atomicAdd(&g_l[b * HH + kv * REP + threadIdx.x], L);
    }
}

// ---------------- kernel 4: output projection (colpair, z=2, STG partials) ----------------
// grid (8, 64, 2), block 128. Normalizes during smem fill.
__global__ void __launch_bounds__(128) proj_o_kernel(const float* __restrict__ wo) {
    __shared__ ULL xs2[DCH][10];
    const int d0 = blockIdx.y * DCH;
    const int b0 = blockIdx.z * 8;
    {
        int i  = threadIdx.x;
        int b  = i / (DCH / 4);
        int d4 = i % (DCH / 4);
        float4 v = *(const float4*)(&g_ao[b0 + b][d0 + d4 * 4]);
        float inv = 1.f / g_l[(b0 + b) * HH + (d0 >> 7)];
        float vx = v.x * inv, vy = v.y * inv, vz = v.z * inv, vw = v.w * inv;
        xs2[d4 * 4 + 0][b] = pack2(vx, vx);
        xs2[d4 * 4 + 1][b] = pack2(vy, vy);
        xs2[d4 * 4 + 2][b] = pack2(vz, vz);
        xs2[d4 * 4 + 3][b] = pack2(vw, vw);
    }
    __syncthreads();

    const int col = (blockIdx.x * 128 + threadIdx.x) * 4;
    const float* w = wo + (size_t)d0 * DDIM + col;

    ULL acc[8][2];
#pragma unroll
    for (int b = 0; b < 8; b++) { acc[b][0] = 0ULL; acc[b][1] = 0ULL; }

    for (int dd = 0; dd < DCH; dd += 4) {
        float4 wv[4];
#pragma unroll
        for (int u = 0; u < 4; u++)
            wv[u] = *(const float4*)(w + (size_t)(dd + u) * DDIM);
#pragma unroll
        for (int u = 0; u < 4; u++) {
            ULL wA = ((const ULL*)&wv[u])[0];
            ULL wB = ((const ULL*)&wv[u])[1];
#pragma unroll
            for (int bp = 0; bp < 4; bp++) {
                ulonglong2 xv = *(const ulonglong2*)&xs2[dd + u][2 * bp];
                acc[2*bp    ][0] = ffma2(xv.x, wA, acc[2*bp    ][0]);
                acc[2*bp    ][1] = ffma2(xv.x, wB, acc[2*bp    ][1]);
                acc[2*bp + 1][0] = ffma2(xv.y, wA, acc[2*bp + 1][0]);
                acc[2*bp + 1][1] = ffma2(xv.y, wB, acc[2*bp + 1][1]);
            }
        }
    }

#pragma unroll
    for (int b = 0; b < 8; b++) {
        float c0, c1, c2, c3;
        unpack2(acc[b][0], c0, c1);
        unpack2(acc[b][1], c2, c3);
        *(float4*)&g_part_out[blockIdx.y][b0 + b][col] = make_float4(c0, c1, c2, c3);
    }
}

// ---------------- kernel 5: reduce output partials -> d_out (float4) ----------------
__global__ void __launch_bounds__(128) reduce_out_kernel(float* __restrict__ out) {
    int idx = blockIdx.x * 128 + threadIdx.x;
    int b  = idx >> 10;
    int c4 = (idx & 1023) << 2;
    float4 s = make_float4(0.f, 0.f, 0.f, 0.f);
#pragma unroll
    for (int ch = 0; ch < NDCH; ch++) {
        float4 v = *(const float4*)&g_part_out[ch][b][c4];
        s.x += v.x; s.y += v.y; s.z += v.z; s.w += v.w;
    }
    *(float4*)&out[b * DDIM + c4] = s;
}

// ---------------- launch ----------------
extern "C" void kernel_launch(void* const* d_in, const int* in_sizes, int n_in,
                              void* d_out, int out_size) {
    const float* x  = (const float*)d_in[0];
    const float* ck = (const float*)d_in[1];
    const float* wq = (const float*)d_in[3];
    const float* wk = (const float*)d_in[4];
    const float* wo = (const float*)d_in[6];
    const float* fc = (const float*)d_in[7];
    const float* fs = (const float*)d_in[8];

    proj_qk_kernel<<<dim3(QK_COLS / 512, NDCH, 2), 128>>>(x, wq, wk);
    rope_kernel<<<(BB * QK_COLS / 2 + 255) / 256, 256>>>(fc, fs);
    attn_kernel<<<dim3(BB * HKV, NSPLIT), 256>>>(ck);
    proj_o_kernel<<<dim3(DDIM / 512, NDCH, 2), 128>>>(wo);
    reduce_out_kernel<<<(BB * DDIM / 4) / 128, 128>>>((float*)d_out);
}

// round 15
// speedup vs baseline: 1.3977x; 1.0314x over previous
#include <cuda_runtime.h>

#define BB 16
#define DDIM 4096
#define HH 32
#define HKV 8
#define DH 128
#define REP 4
#define LL 4096
#define QK_COLS (HH*DH + HKV*DH)   // 5120
#define NSPLIT 16
#define SPLIT_LEN (LL/NSPLIT)      // 256
#define NDCH 64
#define DCH (DDIM/NDCH)            // 64

typedef unsigned long long ULL;

// ---------------- scratch ----------------
__device__ float g_part_qk[NDCH][BB][QK_COLS];
__device__ float g_q[BB][HH][DH];         // roped q, pre-scaled by log2(e)/sqrt(128)
__device__ float g_knew[BB][HKV][DH];
__device__ float g_ao[BB][HH*DH];
__device__ float g_l[BB*HH];
__device__ float g_part_out[NDCH][BB][DDIM];

// ---------------- helpers ----------------
__device__ __forceinline__ ULL pack2(float lo, float hi) {
    ULL r;
    asm("mov.b64 %0, {%1, %2};" : "=l"(r) : "f"(lo), "f"(hi));
    return r;
}
__device__ __forceinline__ void unpack2(ULL v, float& lo, float& hi) {
    asm("mov.b64 {%0, %1}, %2;" : "=f"(lo), "=f"(hi) : "l"(v));
}
__device__ __forceinline__ ULL ffma2(ULL a, ULL b, ULL c) {
    ULL d;
    asm("fma.rn.f32x2 %0, %1, %2, %3;" : "=l"(d) : "l"(a), "l"(b), "l"(c));
    return d;
}
__device__ __forceinline__ ULL add2(ULL a, ULL b) {
    ULL d;
    asm("add.rn.f32x2 %0, %1, %2;" : "=l"(d) : "l"(a), "l"(b));
    return d;
}
__device__ __forceinline__ float ex2(float x) {
    float r;
    asm("ex2.approx.f32 %0, %1;" : "=f"(r) : "f"(x));
    return r;
}

// ---------------- kernel 1: fused Q/K projection (colpair, z=2, STG partials) ----------------
// grid (10, 64, 2), block 128.
__global__ void __launch_bounds__(128) proj_qk_kernel(const float* __restrict__ x,
                                                      const float* __restrict__ wq,
                                                      const float* __restrict__ wk) {
    __shared__ ULL xs2[DCH][10];
    const int d0 = blockIdx.y * DCH;
    const int b0 = blockIdx.z * 8;

    {
        int i  = threadIdx.x;
        int b  = i / (DCH / 4);
        int d4 = i % (DCH / 4);
        float4 v = *(const float4*)(x + (size_t)(b0 + b) * DDIM + d0 + d4 * 4);
        xs2[d4 * 4 + 0][b] = pack2(v.x, v.x);
        xs2[d4 * 4 + 1][b] = pack2(v.y, v.y);
        xs2[d4 * 4 + 2][b] = pack2(v.z, v.z);
        xs2[d4 * 4 + 3][b] = pack2(v.w, v.w);
    }
    __syncthreads();

    const int col = (blockIdx.x * 128 + threadIdx.x) * 4;
    const float* w;
    int stride;
    if (col < HH * DH) { w = wq + col;              stride = HH * DH; }
    else               { w = wk + (col - HH * DH);  stride = HKV * DH; }
    w += (size_t)d0 * stride;

    ULL acc[8][2];
#pragma unroll
    for (int b = 0; b < 8; b++) { acc[b][0] = 0ULL; acc[b][1] = 0ULL; }

    for (int dd = 0; dd < DCH; dd += 4) {
        float4 wv[4];
#pragma unroll
        for (int u = 0; u < 4; u++)
            wv[u] = *(const float4*)(w + (size_t)(dd + u) * stride);
#pragma unroll
        for (int u = 0; u < 4; u++) {
            ULL wA = ((const ULL*)&wv[u])[0];
            ULL wB = ((const ULL*)&wv[u])[1];
#pragma unroll
            for (int bp = 0; bp < 4; bp++) {
                ulonglong2 xv = *(const ulonglong2*)&xs2[dd + u][2 * bp];
                acc[2*bp    ][0] = ffma2(xv.x, wA, acc[2*bp    ][0]);
                acc[2*bp    ][1] = ffma2(xv.x, wB, acc[2*bp    ][1]);
                acc[2*bp + 1][0] = ffma2(xv.y, wA, acc[2*bp + 1][0]);
                acc[2*bp + 1][1] = ffma2(xv.y, wB, acc[2*bp + 1][1]);
            }
        }
    }

#pragma unroll
    for (int b = 0; b < 8; b++) {
        float c0, c1, c2, c3;
        unpack2(acc[b][0], c0, c1);
        unpack2(acc[b][1], c2, c3);
        *(float4*)&g_part_qk[blockIdx.y][b0 + b][col] = make_float4(c0, c1, c2, c3);
    }
}

// ---------------- kernel 2: reduce chunks + RoPE; zero g_ao / g_l ----------------
__global__ void rope_kernel(const float* __restrict__ fc, const float* __restrict__ fs) {
    int idx = blockIdx.x * blockDim.x + threadIdx.x;
    const int TOT = BB * QK_COLS / 2;
    if (idx >= TOT) return;

    if (idx < BB * HH * DH / 2)
        *(float2*)&(((float*)g_ao)[idx * 2]) = make_float2(0.f, 0.f);
    if (idx < BB * HH) g_l[idx] = 0.f;

    int b   = idx / (QK_COLS / 2);
    int col = (idx % (QK_COLS / 2)) * 2;

    float e = 0.f, o = 0.f;
#pragma unroll
    for (int ch = 0; ch < NDCH; ch++) {
        float2 v = *(const float2*)&g_part_qk[ch][b][col];
        e += v.x; o += v.y;
    }
    int p = (col & (DH - 1)) >> 1;
    float c = fc[p], s = fs[p];
    float re = e * c - o * s;
    float ro = e * s + o * c;

    if (col < HH * DH) {
        const float sc = 0.1275174260809843f;   // log2(e)/sqrt(128): scores in log2 domain
        ((float*)g_q)[b * HH * DH + col]     = re * sc;
        ((float*)g_q)[b * HH * DH + col + 1] = ro * sc;
    } else {
        int kc = col - HH * DH;
        ((float*)g_knew)[b * HKV * DH + kc]     = re;
        ((float*)g_knew)[b * HKV * DH + kc + 1] = ro;
    }
}

// ---------------- kernel 3: flash-decode attention (V == K), no-max softmax ----------------
// grid (B*HKV, NSPLIT), block 256 (8 warps), occupancy 2.
// cp.async 4-stage x 4-row per-warp pipeline (3 outstanding groups, wait_group 2).
// Compute body = R8 geometry (rg/dl) with ex2 log2-domain scores.
// Stage smem (64KB) is reused as the merge buffer after the main loop.
__global__ void __launch_bounds__(256, 2) attn_kernel(const float* __restrict__ cache_k) {
    const int b     = blockIdx.x / HKV;
    const int kv    = blockIdx.x % HKV;
    const int split = blockIdx.y;
    const int warp  = threadIdx.x >> 5;
    const int lane  = threadIdx.x & 31;
    const int rg    = lane >> 4;
    const int dl    = lane & 15;

    __shared__ float st[8][4][4][DH];     // 64KB staging; aliased as sm_acc later
    __shared__ float sm_l[8][REP];

    ULL qp0[2][4], qp1[2][4];
#pragma unroll
    for (int hp = 0; hp < 2; hp++) {
        float4 a0 = *(const float4*)&g_q[b][kv*REP + 2*hp    ][dl * 4];
        float4 b0 = *(const float4*)&g_q[b][kv*REP + 2*hp + 1][dl * 4];
        float4 a1 = *(const float4*)&g_q[b][kv*REP + 2*hp    ][64 + dl * 4];
        float4 b1 = *(const float4*)&g_q[b][kv*REP + 2*hp + 1][64 + dl * 4];
        qp0[hp][0] = pack2(a0.x, b0.x); qp0[hp][1] = pack2(a0.y, b0.y);
        qp0[hp][2] = pack2(a0.z, b0.z); qp0[hp][3] = pack2(a0.w, b0.w);
        qp1[hp][0] = pack2(a1.x, b1.x); qp1[hp][1] = pack2(a1.y, b1.y);
        qp1[hp][2] = pack2(a1.z, b1.z); qp1[hp][3] = pack2(a1.w, b1.w);
    }

    ULL acc0[2][4], acc1[2][4];
#pragma unroll
    for (int hp = 0; hp < 2; hp++)
#pragma unroll
        for (int j = 0; j < 4; j++) { acc0[hp][j] = 0ULL; acc1[hp][j] = 0ULL; }
    ULL l2a = 0ULL, l2b = 0ULL;

    const float* kbase = cache_k + (size_t)b * LL * (HKV * DH) + kv * DH;
    const float* knewp = &g_knew[b][kv][0];
    const int sbase = split * SPLIT_LEN + warp * 32;

    const int r_ld = lane >> 3;
    const int coff = (lane & 7) * 16;
    const unsigned stb = (unsigned)__cvta_generic_to_shared(&st[warp][0][0][0]);

#define LOAD_STAGE(BUF, S0)                                                        \
    {                                                                              \
        int s_ = (S0) + r_ld;                                                      \
        const char* src_ = (const char*)((s_ == LL - 1) ? knewp                    \
                              : (kbase + (size_t)s_ * (HKV * DH)));                \
        unsigned dst_ = stb + (BUF) * 2048 + r_ld * 512 + coff;                    \
        _Pragma("unroll")                                                          \
        for (int c_ = 0; c_ < 4; c_++)                                             \
            asm volatile("cp.async.cg.shared.global [%0], [%1], 16;"               \
                         :: "r"(dst_ + c_ * 128), "l"(src_ + coff + c_ * 128)      \
                         : "memory");                                              \
    }

    LOAD_STAGE(0, sbase)
    asm volatile("cp.async.commit_group;" ::: "memory");
    LOAD_STAGE(1, sbase + 4)
    asm volatile("cp.async.commit_group;" ::: "memory");
    LOAD_STAGE(2, sbase + 8)
    asm volatile("cp.async.commit_group;" ::: "memory");

    for (int g = 0; g < 8; g++) {
        asm volatile("cp.async.wait_group 2;" ::: "memory");
        __syncwarp();
        const float* bufp = &st[warp][g & 3][0][0];
#pragma unroll
        for (int it = 0; it < 2; it++) {
            const float* rp = bufp + (it * 2 + rg) * DH;
            float4 k0 = *(const float4*)(rp + dl * 4);
            float4 k1 = *(const float4*)(rp + 64 + dl * 4);

            ULL kd[8];
            kd[0] = pack2(k0.x, k0.x); kd[1] = pack2(k0.y, k0.y);
            kd[2] = pack2(k0.z, k0.z); kd[3] = pack2(k0.w, k0.w);
            kd[4] = pack2(k1.x, k1.x); kd[5] = pack2(k1.y, k1.y);
            kd[6] = pack2(k1.z, k1.z); kd[7] = pack2(k1.w, k1.w);

            ULL sa = 0ULL, sb = 0ULL;
#pragma unroll
            for (int j = 0; j < 4; j++) {
                sa = ffma2(qp0[0][j], kd[j], sa);
                sb = ffma2(qp0[1][j], kd[j], sb);
                sa = ffma2(qp1[0][j], kd[4 + j], sa);
                sb = ffma2(qp1[1][j], kd[4 + j], sb);
            }
            float s0f, s1f, s2f, s3f;
            unpack2(sa, s0f, s1f);
            unpack2(sb, s2f, s3f);
#pragma unroll
            for (int off = 1; off <= 8; off <<= 1) {
                s0f += __shfl_xor_sync(0xffffffffu, s0f, off);
                s1f += __shfl_xor_sync(0xffffffffu, s1f, off);
                s2f += __shfl_xor_sync(0xffffffffu, s2f, off);
                s3f += __shfl_xor_sync(0xffffffffu, s3f, off);
            }
            float p0 = ex2(s0f), p1 = ex2(s1f);
            float p2 = ex2(s2f), p3 = ex2(s3f);
            ULL pp0 = pack2(p0, p1);
            ULL pp1 = pack2(p2, p3);
            l2a = add2(l2a, pp0);
            l2b = add2(l2b, pp1);
#pragma unroll
            for (int j = 0; j < 4; j++) {
                acc0[0][j] = ffma2(pp0, kd[j],     acc0[0][j]);
                acc0[1][j] = ffma2(pp1, kd[j],     acc0[1][j]);
                acc1[0][j] = ffma2(pp0, kd[4 + j], acc1[0][j]);
                acc1[1][j] = ffma2(pp1, kd[4 + j], acc1[1][j]);
            }
        }
        __syncwarp();   // all lanes done reading before the buffer slot is refilled
        if (g < 5) LOAD_STAGE((g + 3) & 3, sbase + (g + 3) * 4)
        asm volatile("cp.async.commit_group;" ::: "memory");
    }
#undef LOAD_STAGE

    float a[4][8], l[4];
#pragma unroll
    for (int j = 0; j < 4; j++) {
        unpack2(acc0[0][j], a[0][j], a[1][j]);
        unpack2(acc0[1][j], a[2][j], a[3][j]);
        unpack2(acc1[0][j], a[0][4 + j], a[1][4 + j]);
        unpack2(acc1[1][j], a[2][4 + j], a[3][4 + j]);
    }
    unpack2(l2a, l[0], l[1]);
    unpack2(l2b, l[2], l[3]);

#pragma unroll
    for (int h = 0; h < 4; h++) {
        l[h] += __shfl_xor_sync(0xffffffffu, l[h], 16);
#pragma unroll
        for (int j = 0; j < 8; j++)
            a[h][j] += __shfl_xor_sync(0xffffffffu, a[h][j], 16);
    }

    __syncthreads();    // all warps done with staging smem — safe to alias
    float (*sm_acc)[REP][DH] = (float (*)[REP][DH])st;
    if (rg == 0) {
#pragma unroll
        for (int h = 0; h < 4; h++) {
            *(float4*)&sm_acc[warp][h][dl * 4]      = make_float4(a[h][0], a[h][1], a[h][2], a[h][3]);
            *(float4*)&sm_acc[warp][h][64 + dl * 4] = make_float4(a[h][4], a[h][5], a[h][6], a[h][7]);
        }
    }
    if (lane == 0) {
#pragma unroll
        for (int h = 0; h < 4; h++) sm_l[warp][h] = l[h];
    }
    __syncthreads();

    for (int item = threadIdx.x; item < REP * DH; item += 256) {
        int h = item >> 7, d = item & (DH - 1);
        float O = 0.f;
#pragma unroll
        for (int w = 0; w < 8; w++) O += sm_acc[w][h][d];
        atomicAdd(&g_ao[b][(kv * REP + h) * DH + d], O);
    }
    if (threadIdx.x < REP) {
        float L = 0.f;
#pragma unroll
        for (int w = 0; w < 8; w++) L += sm_l[w][threadIdx.x];
        atomicAdd(&g_l[b * HH + kv * REP + threadIdx.x], L);
    }
}

// ---------------- kernel 4: output projection (colpair, z=2, STG partials) ----------------
// grid (8, 64, 2), block 128. Normalizes during smem fill.
__global__ void __launch_bounds__(128) proj_o_kernel(const float* __restrict__ wo) {
    __shared__ ULL xs2[DCH][10];
    const int d0 = blockIdx.y * DCH;
    const int b0 = blockIdx.z * 8;
    {
        int i  = threadIdx.x;
        int b  = i / (DCH / 4);
        int d4 = i % (DCH / 4);
        float4 v = *(const float4*)(&g_ao[b0 + b][d0 + d4 * 4]);
        float inv = 1.f / g_l[(b0 + b) * HH + (d0 >> 7)];
        float vx = v.x * inv, vy = v.y * inv, vz = v.z * inv, vw = v.w * inv;
        xs2[d4 * 4 + 0][b] = pack2(vx, vx);
        xs2[d4 * 4 + 1][b] = pack2(vy, vy);
        xs2[d4 * 4 + 2][b] = pack2(vz, vz);
        xs2[d4 * 4 + 3][b] = pack2(vw, vw);
    }
    __syncthreads();

    const int col = (blockIdx.x * 128 + threadIdx.x) * 4;
    const float* w = wo + (size_t)d0 * DDIM + col;

    ULL acc[8][2];
#pragma unroll
    for (int b = 0; b < 8; b++) { acc[b][0] = 0ULL; acc[b][1] = 0ULL; }

    for (int dd = 0; dd < DCH; dd += 4) {
        float4 wv[4];
#pragma unroll
        for (int u = 0; u < 4; u++)
            wv[u] = *(const float4*)(w + (size_t)(dd + u) * DDIM);
#pragma unroll
        for (int u = 0; u < 4; u++) {
            ULL wA = ((const ULL*)&wv[u])[0];
            ULL wB = ((const ULL*)&wv[u])[1];
#pragma unroll
            for (int bp = 0; bp < 4; bp++) {
                ulonglong2 xv = *(const ulonglong2*)&xs2[dd + u][2 * bp];
                acc[2*bp    ][0] = ffma2(xv.x, wA, acc[2*bp    ][0]);
                acc[2*bp    ][1] = ffma2(xv.x, wB, acc[2*bp    ][1]);
                acc[2*bp + 1][0] = ffma2(xv.y, wA, acc[2*bp + 1][0]);
                acc[2*bp + 1][1] = ffma2(xv.y, wB, acc[2*bp + 1][1]);
            }
        }
    }

#pragma unroll
    for (int b = 0; b < 8; b++) {
        float c0, c1, c2, c3;
        unpack2(acc[b][0], c0, c1);
        unpack2(acc[b][1], c2, c3);
        *(float4*)&g_part_out[blockIdx.y][b0 + b][col] = make_float4(c0, c1, c2, c3);
    }
}

// ---------------- kernel 5: reduce output partials -> d_out (float4) ----------------
__global__ void __launch_bounds__(128) reduce_out_kernel(float* __restrict__ out) {
    int idx = blockIdx.x * 128 + threadIdx.x;
    int b  = idx >> 10;
    int c4 = (idx & 1023) << 2;
    float4 s = make_float4(0.f, 0.f, 0.f, 0.f);
#pragma unroll
    for (int ch = 0; ch < NDCH; ch++) {
        float4 v = *(const float4*)&g_part_out[ch][b][c4];
        s.x += v.x; s.y += v.y; s.z += v.z; s.w += v.w;
    }
    *(float4*)&out[b * DDIM + c4] = s;
}

// ---------------- launch ----------------
extern "C" void kernel_launch(void* const* d_in, const int* in_sizes, int n_in,
                              void* d_out, int out_size) {
    const float* x  = (const float*)d_in[0];
    const float* ck = (const float*)d_in[1];
    const float* wq = (const float*)d_in[3];
    const float* wk = (const float*)d_in[4];
    const float* wo = (const float*)d_in[6];
    const float* fc = (const float*)d_in[7];
    const float* fs = (const float*)d_in[8];

    proj_qk_kernel<<<dim3(QK_COLS / 512, NDCH, 2), 128>>>(x, wq, wk);
    rope_kernel<<<(BB * QK_COLS / 2 + 255) / 256, 256>>>(fc, fs);
    attn_kernel<<<dim3(BB * HKV, NSPLIT), 256>>>(ck);
    proj_o_kernel<<<dim3(DDIM / 512, NDCH, 2), 128>>>(wo);
    reduce_out_kernel<<<(BB * DDIM / 4) / 128, 128>>>((float*)d_out);
}

// round 16
// speedup vs baseline: 1.5282x; 1.0933x over previous
#include <cuda_runtime.h>

#define BB 16
#define DDIM 4096
#define HH 32
#define HKV 8
#define DH 128
#define REP 4
#define LL 4096
#define QK_COLS (HH*DH + HKV*DH)   // 5120
#define NSPLIT 8
#define SPLIT_LEN (LL/NSPLIT)      // 512
#define NDCH 64
#define DCH (DDIM/NDCH)            // 64

typedef unsigned long long ULL;

// ---------------- scratch ----------------
__device__ float g_part_qk[NDCH][BB][QK_COLS];
__device__ float g_q[BB][HH][DH];         // roped q, pre-scaled by log2(e)/sqrt(128)
__device__ float g_knew[BB][HKV][DH];
__device__ float g_ao[BB][HH*DH];
__device__ float g_l[BB*HH];
__device__ float g_part_out[NDCH][BB][DDIM];

// ---------------- helpers ----------------
__device__ __forceinline__ ULL pack2(float lo, float hi) {
    ULL r;
    asm("mov.b64 %0, {%1, %2};" : "=l"(r) : "f"(lo), "f"(hi));
    return r;
}
__device__ __forceinline__ void unpack2(ULL v, float& lo, float& hi) {
    asm("mov.b64 {%0, %1}, %2;" : "=f"(lo), "=f"(hi) : "l"(v));
}
__device__ __forceinline__ ULL ffma2(ULL a, ULL b, ULL c) {
    ULL d;
    asm("fma.rn.f32x2 %0, %1, %2, %3;" : "=l"(d) : "l"(a), "l"(b), "l"(c));
    return d;
}
__device__ __forceinline__ ULL add2(ULL a, ULL b) {
    ULL d;
    asm("add.rn.f32x2 %0, %1, %2;" : "=l"(d) : "l"(a), "l"(b));
    return d;
}
__device__ __forceinline__ float ex2(float x) {
    float r;
    asm("ex2.approx.f32 %0, %1;" : "=f"(r) : "f"(x));
    return r;
}

// ---------------- kernel 1: fused Q/K projection (colpair, z=2, cp.async weights) ----------------
// grid (10, 64, 2), block 128. Per-thread weight stream through smem: 2 buf x 8 rows,
// thread consumes only its own staged 16B per row -> no barriers needed.
__global__ void __launch_bounds__(128) proj_qk_kernel(const float* __restrict__ x,
                                                      const float* __restrict__ wq,
                                                      const float* __restrict__ wk) {
    __shared__ ULL xs2[DCH][10];
    __shared__ char wst[2][8][2048];     // 32KB weight staging
    const int d0 = blockIdx.y * DCH;
    const int b0 = blockIdx.z * 8;
    const int t  = threadIdx.x;

    {
        int b  = t / (DCH / 4);
        int d4 = t % (DCH / 4);
        float4 v = *(const float4*)(x + (size_t)(b0 + b) * DDIM + d0 + d4 * 4);
        xs2[d4 * 4 + 0][b] = pack2(v.x, v.x);
        xs2[d4 * 4 + 1][b] = pack2(v.y, v.y);
        xs2[d4 * 4 + 2][b] = pack2(v.z, v.z);
        xs2[d4 * 4 + 3][b] = pack2(v.w, v.w);
    }
    __syncthreads();

    const int col = (blockIdx.x * 128 + t) * 4;
    const float* w;
    int stride;
    if (col < HH * DH) { w = wq + col;              stride = HH * DH; }
    else               { w = wk + (col - HH * DH);  stride = HKV * DH; }
    w += (size_t)d0 * stride;

    const unsigned wstb = (unsigned)__cvta_generic_to_shared(&wst[0][0][0]) + t * 16;

#define LOADW(BUF, R0)                                                            \
    {                                                                             \
        _Pragma("unroll")                                                         \
        for (int r_ = 0; r_ < 8; r_++)                                            \
            asm volatile("cp.async.cg.shared.global [%0], [%1], 16;"              \
                         :: "r"(wstb + (BUF) * 16384 + r_ * 2048),                \
                            "l"((const char*)(w + (size_t)((R0) + r_) * stride))  \
                         : "memory");                                             \
        asm volatile("cp.async.commit_group;" ::: "memory");                      \
    }

    ULL acc[8][2];
#pragma unroll
    for (int b = 0; b < 8; b++) { acc[b][0] = 0ULL; acc[b][1] = 0ULL; }

    LOADW(0, 0)
    LOADW(1, 8)

    for (int st = 0; st < 8; st++) {
        asm volatile("cp.async.wait_group 1;" ::: "memory");
        const char* bufp = &wst[st & 1][0][0] + t * 16;
#pragma unroll
        for (int r = 0; r < 8; r++) {
            float4 wv = *(const float4*)(bufp + r * 2048);
            ULL wA = ((const ULL*)&wv)[0];
            ULL wB = ((const ULL*)&wv)[1];
            const int dd = st * 8 + r;
#pragma unroll
            for (int bp = 0; bp < 4; bp++) {
                ulonglong2 xv = *(const ulonglong2*)&xs2[dd][2 * bp];
                acc[2*bp    ][0] = ffma2(xv.x, wA, acc[2*bp    ][0]);
                acc[2*bp    ][1] = ffma2(xv.x, wB, acc[2*bp    ][1]);
                acc[2*bp + 1][0] = ffma2(xv.y, wA, acc[2*bp + 1][0]);
                acc[2*bp + 1][1] = ffma2(xv.y, wB, acc[2*bp + 1][1]);
            }
        }
        if (st < 6) LOADW(st & 1, (st + 2) * 8)
        else asm volatile("cp.async.commit_group;" ::: "memory");
    }
#undef LOADW

#pragma unroll
    for (int b = 0; b < 8; b++) {
        float c0, c1, c2, c3;
        unpack2(acc[b][0], c0, c1);
        unpack2(acc[b][1], c2, c3);
        *(float4*)&g_part_qk[blockIdx.y][b0 + b][col] = make_float4(c0, c1, c2, c3);
    }
}

// ---------------- kernel 2: reduce chunks + RoPE; zero g_ao / g_l ----------------
__global__ void rope_kernel(const float* __restrict__ fc, const float* __restrict__ fs) {
    int idx = blockIdx.x * blockDim.x + threadIdx.x;
    const int TOT = BB * QK_COLS / 2;
    if (idx >= TOT) return;

    if (idx < BB * HH * DH / 2)
        *(float2*)&(((float*)g_ao)[idx * 2]) = make_float2(0.f, 0.f);
    if (idx < BB * HH) g_l[idx] = 0.f;

    int b   = idx / (QK_COLS / 2);
    int col = (idx % (QK_COLS / 2)) * 2;

    float e = 0.f, o = 0.f;
#pragma unroll
    for (int ch = 0; ch < NDCH; ch++) {
        float2 v = *(const float2*)&g_part_qk[ch][b][col];
        e += v.x; o += v.y;
    }
    int p = (col & (DH - 1)) >> 1;
    float c = fc[p], s = fs[p];
    float re = e * c - o * s;
    float ro = e * s + o * c;

    if (col < HH * DH) {
        const float sc = 0.1275174260809843f;   // log2(e)/sqrt(128)
        ((float*)g_q)[b * HH * DH + col]     = re * sc;
        ((float*)g_q)[b * HH * DH + col + 1] = ro * sc;
    } else {
        int kc = col - HH * DH;
        ((float*)g_knew)[b * HKV * DH + kc]     = re;
        ((float*)g_knew)[b * HKV * DH + kc + 1] = ro;
    }
}

// ---------------- kernel 3: flash-decode attention (V == K), no-max softmax ----------------
// grid (B*HKV, 8), block 256 (8 warps), occupancy 2. SPLIT_LEN=512 -> 64 rows/warp.
// cp.async 4-stage x 4-row per-warp pipeline (wait_group 2); R8 geometry, ex2 scores.
__global__ void __launch_bounds__(256, 2) attn_kernel(const float* __restrict__ cache_k) {
    const int b     = blockIdx.x / HKV;
    const int kv    = blockIdx.x % HKV;
    const int split = blockIdx.y;
    const int warp  = threadIdx.x >> 5;
    const int lane  = threadIdx.x & 31;
    const int rg    = lane >> 4;
    const int dl    = lane & 15;

    __shared__ float st[8][4][4][DH];     // 64KB staging; aliased as sm_acc later
    __shared__ float sm_l[8][REP];

    ULL qp0[2][4], qp1[2][4];
#pragma unroll
    for (int hp = 0; hp < 2; hp++) {
        float4 a0 = *(const float4*)&g_q[b][kv*REP + 2*hp    ][dl * 4];
        float4 b0 = *(const float4*)&g_q[b][kv*REP + 2*hp + 1][dl * 4];
        float4 a1 = *(const float4*)&g_q[b][kv*REP + 2*hp    ][64 + dl * 4];
        float4 b1 = *(const float4*)&g_q[b][kv*REP + 2*hp + 1][64 + dl * 4];
        qp0[hp][0] = pack2(a0.x, b0.x); qp0[hp][1] = pack2(a0.y, b0.y);
        qp0[hp][2] = pack2(a0.z, b0.z); qp0[hp][3] = pack2(a0.w, b0.w);
        qp1[hp][0] = pack2(a1.x, b1.x); qp1[hp][1] = pack2(a1.y, b1.y);
        qp1[hp][2] = pack2(a1.z, b1.z); qp1[hp][3] = pack2(a1.w, b1.w);
    }

    ULL acc0[2][4], acc1[2][4];
#pragma unroll
    for (int hp = 0; hp < 2; hp++)
#pragma unroll
        for (int j = 0; j < 4; j++) { acc0[hp][j] = 0ULL; acc1[hp][j] = 0ULL; }
    ULL l2a = 0ULL, l2b = 0ULL;

    const float* kbase = cache_k + (size_t)b * LL * (HKV * DH) + kv * DH;
    const float* knewp = &g_knew[b][kv][0];
    const int sbase = split * SPLIT_LEN + warp * 64;

    const int r_ld = lane >> 3;
    const int coff = (lane & 7) * 16;
    const unsigned stb = (unsigned)__cvta_generic_to_shared(&st[warp][0][0][0]);

#define LOAD_STAGE(BUF, S0)                                                        \
    {                                                                              \
        int s_ = (S0) + r_ld;                                                      \
        const char* src_ = (const char*)((s_ == LL - 1) ? knewp                    \
                              : (kbase + (size_t)s_ * (HKV * DH)));                \
        unsigned dst_ = stb + (BUF) * 2048 + r_ld * 512 + coff;                    \
        _Pragma("unroll")                                                          \
        for (int c_ = 0; c_ < 4; c_++)                                             \
            asm volatile("cp.async.cg.shared.global [%0], [%1], 16;"               \
                         :: "r"(dst_ + c_ * 128), "l"(src_ + coff + c_ * 128)      \
                         : "memory");                                              \
    }

    LOAD_STAGE(0, sbase)
    asm volatile("cp.async.commit_group;" ::: "memory");
    LOAD_STAGE(1, sbase + 4)
    asm volatile("cp.async.commit_group;" ::: "memory");
    LOAD_STAGE(2, sbase + 8)
    asm volatile("cp.async.commit_group;" ::: "memory");

    for (int g = 0; g < 16; g++) {
        asm volatile("cp.async.wait_group 2;" ::: "memory");
        __syncwarp();
        const float* bufp = &st[warp][g & 3][0][0];
#pragma unroll
        for (int it = 0; it < 2; it++) {
            const float* rp = bufp + (it * 2 + rg) * DH;
            float4 k0 = *(const float4*)(rp + dl * 4);
            float4 k1 = *(const float4*)(rp + 64 + dl * 4);

            ULL kd[8];
            kd[0] = pack2(k0.x, k0.x); kd[1] = pack2(k0.y, k0.y);
            kd[2] = pack2(k0.z, k0.z); kd[3] = pack2(k0.w, k0.w);
            kd[4] = pack2(k1.x, k1.x); kd[5] = pack2(k1.y, k1.y);
            kd[6] = pack2(k1.z, k1.z); kd[7] = pack2(k1.w, k1.w);

            ULL sa = 0ULL, sb = 0ULL;
#pragma unroll
            for (int j = 0; j < 4; j++) {
                sa = ffma2(qp0[0][j], kd[j], sa);
                sb = ffma2(qp0[1][j], kd[j], sb);
                sa = ffma2(qp1[0][j], kd[4 + j], sa);
                sb = ffma2(qp1[1][j], kd[4 + j], sb);
            }
            float s0f, s1f, s2f, s3f;
            unpack2(sa, s0f, s1f);
            unpack2(sb, s2f, s3f);
#pragma unroll
            for (int off = 1; off <= 8; off <<= 1) {
                s0f += __shfl_xor_sync(0xffffffffu, s0f, off);
                s1f += __shfl_xor_sync(0xffffffffu, s1f, off);
                s2f += __shfl_xor_sync(0xffffffffu, s2f, off);
                s3f += __shfl_xor_sync(0xffffffffu, s3f, off);
            }
            float p0 = ex2(s0f), p1 = ex2(s1f);
            float p2 = ex2(s2f), p3 = ex2(s3f);
            ULL pp0 = pack2(p0, p1);
            ULL pp1 = pack2(p2, p3);
            l2a = add2(l2a, pp0);
            l2b = add2(l2b, pp1);
#pragma unroll
            for (int j = 0; j < 4; j++) {
                acc0[0][j] = ffma2(pp0, kd[j],     acc0[0][j]);
                acc0[1][j] = ffma2(pp1, kd[j],     acc0[1][j]);
                acc1[0][j] = ffma2(pp0, kd[4 + j], acc1[0][j]);
                acc1[1][j] = ffma2(pp1, kd[4 + j], acc1[1][j]);
            }
        }
        __syncwarp();
        if (g < 13) LOAD_STAGE((g + 3) & 3, sbase + (g + 3) * 4)
        asm volatile("cp.async.commit_group;" ::: "memory");
    }
#undef LOAD_STAGE

    float a[4][8], l[4];
#pragma unroll
    for (int j = 0; j < 4; j++) {
        unpack2(acc0[0][j], a[0][j], a[1][j]);
        unpack2(acc0[1][j], a[2][j], a[3][j]);
        unpack2(acc1[0][j], a[0][4 + j], a[1][4 + j]);
        unpack2(acc1[1][j], a[2][4 + j], a[3][4 + j]);
    }
    unpack2(l2a, l[0], l[1]);
    unpack2(l2b, l[2], l[3]);

#pragma unroll
    for (int h = 0; h < 4; h++) {
        l[h] += __shfl_xor_sync(0xffffffffu, l[h], 16);
#pragma unroll
        for (int j = 0; j < 8; j++)
            a[h][j] += __shfl_xor_sync(0xffffffffu, a[h][j], 16);
    }

    __syncthreads();
    float (*sm_acc)[REP][DH] = (float (*)[REP][DH])st;
    if (rg == 0) {
#pragma unroll
        for (int h = 0; h < 4; h++) {
            *(float4*)&sm_acc[warp][h][dl * 4]      = make_float4(a[h][0], a[h][1], a[h][2], a[h][3]);
            *(float4*)&sm_acc[warp][h][64 + dl * 4] = make_float4(a[h][4], a[h][5], a[h][6], a[h][7]);
        }
    }
    if (lane == 0) {
#pragma unroll
        for (int h = 0; h < 4; h++) sm_l[warp][h] = l[h];
    }
    __syncthreads();

    for (int item = threadIdx.x; item < REP * DH; item += 256) {
        int h = item >> 7, d = item & (DH - 1);
        float O = 0.f;
#pragma unroll
        for (int w = 0; w < 8; w++) O += sm_acc[w][h][d];
        atomicAdd(&g_ao[b][(kv * REP + h) * DH + d], O);
    }
    if (threadIdx.x < REP) {
        float L = 0.f;
#pragma unroll
        for (int w = 0; w < 8; w++) L += sm_l[w][threadIdx.x];
        atomicAdd(&g_l[b * HH + kv * REP + threadIdx.x], L);
    }
}

// ---------------- kernel 4: output projection (colpair, z=2, cp.async weights) ----------------
// grid (8, 64, 2), block 128.
__global__ void __launch_bounds__(128) proj_o_kernel(const float* __restrict__ wo) {
    __shared__ ULL xs2[DCH][10];
    __shared__ char wst[2][8][2048];
    const int d0 = blockIdx.y * DCH;
    const int b0 = blockIdx.z * 8;
    const int t  = threadIdx.x;
    {
        int b  = t / (DCH / 4);
        int d4 = t % (DCH / 4);
        float4 v = *(const float4*)(&g_ao[b0 + b][d0 + d4 * 4]);
        float inv = 1.f / g_l[(b0 + b) * HH + (d0 >> 7)];
        float vx = v.x * inv, vy = v.y * inv, vz = v.z * inv, vw = v.w * inv;
        xs2[d4 * 4 + 0][b] = pack2(vx, vx);
        xs2[d4 * 4 + 1][b] = pack2(vy, vy);
        xs2[d4 * 4 + 2][b] = pack2(vz, vz);
        xs2[d4 * 4 + 3][b] = pack2(vw, vw);
    }
    __syncthreads();

    const int col = (blockIdx.x * 128 + t) * 4;
    const float* w = wo + (size_t)d0 * DDIM + col;
    const unsigned wstb = (unsigned)__cvta_generic_to_shared(&wst[0][0][0]) + t * 16;

#define LOADW(BUF, R0)                                                            \
    {                                                                             \
        _Pragma("unroll")                                                         \
        for (int r_ = 0; r_ < 8; r_++)                                            \
            asm volatile("cp.async.cg.shared.global [%0], [%1], 16;"              \
                         :: "r"(wstb + (BUF) * 16384 + r_ * 2048),                \
                            "l"((const char*)(w + (size_t)((R0) + r_) * DDIM))    \
                         : "memory");                                             \
        asm volatile("cp.async.commit_group;" ::: "memory");                      \
    }

    ULL acc[8][2];
#pragma unroll
    for (int b = 0; b < 8; b++) { acc[b][0] = 0ULL; acc[b][1] = 0ULL; }

    LOADW(0, 0)
    LOADW(1, 8)

    for (int st = 0; st < 8; st++) {
        asm volatile("cp.async.wait_group 1;" ::: "memory");
        const char* bufp = &wst[st & 1][0][0] + t * 16;
#pragma unroll
        for (int r = 0; r < 8; r++) {
            float4 wv = *(const float4*)(bufp + r * 2048);
            ULL wA = ((const ULL*)&wv)[0];
            ULL wB = ((const ULL*)&wv)[1];
            const int dd = st * 8 + r;
#pragma unroll
            for (int bp = 0; bp < 4; bp++) {
                ulonglong2 xv = *(const ulonglong2*)&xs2[dd][2 * bp];
                acc[2*bp    ][0] = ffma2(xv.x, wA, acc[2*bp    ][0]);
                acc[2*bp    ][1] = ffma2(xv.x, wB, acc[2*bp    ][1]);
                acc[2*bp + 1][0] = ffma2(xv.y, wA, acc[2*bp + 1][0]);
                acc[2*bp + 1][1] = ffma2(xv.y, wB, acc[2*bp + 1][1]);
            }
        }
        if (st < 6) LOADW(st & 1, (st + 2) * 8)
        else asm volatile("cp.async.commit_group;" ::: "memory");
    }
#undef LOADW

#pragma unroll
    for (int b = 0; b < 8; b++) {
        float c0, c1, c2, c3;
        unpack2(acc[b][0], c0, c1);
        unpack2(acc[b][1], c2, c3);
        *(float4*)&g_part_out[blockIdx.y][b0 + b][col] = make_float4(c0, c1, c2, c3);
    }
}

// ---------------- kernel 5: reduce output partials -> d_out (float4) ----------------
__global__ void __launch_bounds__(128) reduce_out_kernel(float* __restrict__ out) {
    int idx = blockIdx.x * 128 + threadIdx.x;
    int b  = idx >> 10;
    int c4 = (idx & 1023) << 2;
    float4 s = make_float4(0.f, 0.f, 0.f, 0.f);
#pragma unroll
    for (int ch = 0; ch < NDCH; ch++) {
        float4 v = *(const float4*)&g_part_out[ch][b][c4];
        s.x += v.x; s.y += v.y; s.z += v.z; s.w += v.w;
    }
    *(float4*)&out[b * DDIM + c4] = s;
}

// ---------------- launch ----------------
extern "C" void kernel_launch(void* const* d_in, const int* in_sizes, int n_in,
                              void* d_out, int out_size) {
    const float* x  = (const float*)d_in[0];
    const float* ck = (const float*)d_in[1];
    const float* wq = (const float*)d_in[3];
    const float* wk = (const float*)d_in[4];
    const float* wo = (const float*)d_in[6];
    const float* fc = (const float*)d_in[7];
    const float* fs = (const float*)d_in[8];

    proj_qk_kernel<<<dim3(QK_COLS / 512, NDCH, 2), 128>>>(x, wq, wk);
    rope_kernel<<<(BB * QK_COLS / 2 + 255) / 256, 256>>>(fc, fs);
    attn_kernel<<<dim3(BB * HKV, NSPLIT), 256>>>(ck);
    proj_o_kernel<<<dim3(DDIM / 512, NDCH, 2), 128>>>(wo);
    reduce_out_kernel<<<(BB * DDIM / 4) / 128, 128>>>((float*)d_out);
}